// round 1
// baseline (speedup 1.0000x reference)
#include <cuda_runtime.h>
#include <math.h>
#include <stdint.h>

#define B_   4
#define S_   2048
#define D_   2048
#define H_   16
#define KVH_ 8
#define HD_  128

// ---------------- scratch (device globals; no allocation allowed) ----------------
__device__ float g_q[(size_t)B_ * S_ * H_ * HD_];     // 64 MB
__device__ float g_k[(size_t)B_ * S_ * KVH_ * HD_];   // 32 MB
__device__ float g_v[(size_t)B_ * S_ * KVH_ * HD_];   // 32 MB
__device__ float g_att[(size_t)B_ * S_ * H_ * HD_];   // 64 MB

// ---------------- generic fp32 SGEMM: C[M,N] = A[M,K] @ B[K,N] ----------------
// 128x128 CTA tile, K-step 8, 256 threads, 8x8 per-thread micro-tile.
// Requires M%128==0, N%128==0, K%8==0 (true for all our shapes).
__global__ __launch_bounds__(256) void sgemm128(const float* __restrict__ A,
                                                const float* __restrict__ B,
                                                float* __restrict__ C,
                                                int M, int N, int K) {
    __shared__ float As[8][128];
    __shared__ float Bs[8][128];

    const int tid = threadIdx.x;
    const int tx = tid & 15;       // 0..15
    const int ty = tid >> 4;       // 0..15
    const int m0 = blockIdx.y * 128;
    const int n0 = blockIdx.x * 128;

    const int arow = tid >> 1;            // 0..127
    const int acol = (tid & 1) << 2;      // 0 or 4
    const int brow = tid >> 5;            // 0..7
    const int bcol = (tid & 31) << 2;     // 0..124

    const float* Aptr = A + (size_t)(m0 + arow) * K + acol;
    const float* Bptr = B + (size_t)brow * N + n0 + bcol;

    float acc[8][8];
#pragma unroll
    for (int i = 0; i < 8; ++i)
#pragma unroll
        for (int j = 0; j < 8; ++j) acc[i][j] = 0.f;

    for (int k0 = 0; k0 < K; k0 += 8) {
        float4 av = *(const float4*)Aptr; Aptr += 8;
        float4 bv = *(const float4*)Bptr; Bptr += (size_t)8 * N;

        __syncthreads();
        As[acol + 0][arow] = av.x;
        As[acol + 1][arow] = av.y;
        As[acol + 2][arow] = av.z;
        As[acol + 3][arow] = av.w;
        *(float4*)&Bs[brow][bcol] = bv;
        __syncthreads();

#pragma unroll
        for (int k = 0; k < 8; ++k) {
            float ar[8], br[8];
            *(float4*)(ar)     = *(const float4*)&As[k][ty * 4];
            *(float4*)(ar + 4) = *(const float4*)&As[k][ty * 4 + 64];
            *(float4*)(br)     = *(const float4*)&Bs[k][tx * 4];
            *(float4*)(br + 4) = *(const float4*)&Bs[k][tx * 4 + 64];
#pragma unroll
            for (int i = 0; i < 8; ++i)
#pragma unroll
                for (int j = 0; j < 8; ++j)
                    acc[i][j] += ar[i] * br[j];
        }
    }

#pragma unroll
    for (int i = 0; i < 8; ++i) {
        int r = m0 + ty * 4 + (i & 3) + ((i >= 4) ? 64 : 0);
        float4 o1 = make_float4(acc[i][0], acc[i][1], acc[i][2], acc[i][3]);
        float4 o2 = make_float4(acc[i][4], acc[i][5], acc[i][6], acc[i][7]);
        *(float4*)&C[(size_t)r * N + n0 + tx * 4]      = o1;
        *(float4*)&C[(size_t)r * N + n0 + tx * 4 + 64] = o2;
    }
}

// ---------------- RoPE (in-place), t: [B, S, nh, HD], pairs interleaved ----------------
__global__ __launch_bounds__(256) void rope_kernel(float* __restrict__ t,
                                                   const float* __restrict__ co,
                                                   const float* __restrict__ si,
                                                   int nh, int npairs) {
    int idx = blockIdx.x * blockDim.x + threadIdx.x;
    if (idx >= npairs) return;
    int i = idx & 63;                       // freq index (HD/2 = 64)
    int s = ((idx >> 6) / nh) % S_;         // sequence position
    float c  = co[s * 64 + i];
    float sn = si[s * 64 + i];
    float2 v = *(float2*)&t[(size_t)idx * 2];
    float2 o;
    o.x = v.x * c - v.y * sn;
    o.y = v.x * sn + v.y * c;
    *(float2*)&t[(size_t)idx * 2] = o;
}

// ---------------- flash attention (fp32), causal, GQA ----------------
// CTA: 128 threads, one 64-row Q tile for one (b, h). KV tiles of 64 rows.
// smem: sQ[64][132], sKV[64][132] (K then V reuse), sP[64][68]  => 84992 B
#define BM 64
#define BN 64
#define QSTR 132
#define PSTR 68

__global__ __launch_bounds__(128) void flash_kernel(const float* __restrict__ Q,
                                                    const float* __restrict__ Kb,
                                                    const float* __restrict__ Vb,
                                                    float* __restrict__ O) {
    extern __shared__ float sm[];
    float* sQ  = sm;                         // 64*132
    float* sKV = sm + 64 * QSTR;             // 64*132
    float* sP  = sm + 2 * 64 * QSTR;         // 64*68

    const int qt = blockIdx.x;
    const int h  = blockIdx.y;
    const int b  = blockIdx.z;
    const int hk = h >> 1;                   // N_REP = 2
    const int tid = threadIdx.x;
    const int tx = tid & 7;                  // 0..7  (8 col-threads)
    const int ty = tid >> 3;                 // 0..15 (16 row-threads, 4 rows each)
    const int q0 = qt * BM;
    const float scale = 0.08838834764831845f; // 1/sqrt(128)

    // load Q tile (pre-scaled)
    for (int i = tid; i < BM * 32; i += 128) {
        int r = i >> 5, c4 = (i & 31) << 2;
        float4 v = *(const float4*)&Q[(((size_t)b * S_ + q0 + r) * H_ + h) * HD_ + c4];
        v.x *= scale; v.y *= scale; v.z *= scale; v.w *= scale;
        *(float4*)&sQ[r * QSTR + c4] = v;
    }

    float m_i[4], l_i[4], acc[4][16];
#pragma unroll
    for (int i = 0; i < 4; ++i) {
        m_i[i] = -1e30f; l_i[i] = 0.f;
#pragma unroll
        for (int c = 0; c < 16; ++c) acc[i][c] = 0.f;
    }

    for (int j = 0; j <= qt; ++j) {
        const int k0 = j * BN;

        __syncthreads();   // protect prior V reads (and first-iter Q stores)
        for (int i = tid; i < BN * 32; i += 128) {
            int r = i >> 5, c4 = (i & 31) << 2;
            *(float4*)&sKV[r * QSTR + c4] =
                *(const float4*)&Kb[(((size_t)b * S_ + k0 + r) * KVH_ + hk) * HD_ + c4];
        }
        __syncthreads();

        // S = Q K^T  (per-thread 4 rows x 8 cols)
        float sa[4][8];
#pragma unroll
        for (int i = 0; i < 4; ++i)
#pragma unroll
            for (int jj = 0; jj < 8; ++jj) sa[i][jj] = 0.f;

#pragma unroll 2
        for (int d = 0; d < HD_; d += 4) {
            float4 qv[4], kv[8];
#pragma unroll
            for (int i = 0; i < 4; ++i)
                qv[i] = *(const float4*)&sQ[(ty * 4 + i) * QSTR + d];
#pragma unroll
            for (int jj = 0; jj < 8; ++jj)
                kv[jj] = *(const float4*)&sKV[(tx + 8 * jj) * QSTR + d];
#pragma unroll
            for (int i = 0; i < 4; ++i)
#pragma unroll
                for (int jj = 0; jj < 8; ++jj) {
                    sa[i][jj] += qv[i].x * kv[jj].x;
                    sa[i][jj] += qv[i].y * kv[jj].y;
                    sa[i][jj] += qv[i].z * kv[jj].z;
                    sa[i][jj] += qv[i].w * kv[jj].w;
                }
        }

        if (j == qt) {   // diagonal tile: causal mask
#pragma unroll
            for (int i = 0; i < 4; ++i)
#pragma unroll
                for (int jj = 0; jj < 8; ++jj)
                    if (tx + 8 * jj > ty * 4 + i) sa[i][jj] = -1e30f;
        }

        // online softmax update (rows owned by (ty,i); reduce across 8 tx lanes)
#pragma unroll
        for (int i = 0; i < 4; ++i) {
            float mt = sa[i][0];
#pragma unroll
            for (int jj = 1; jj < 8; ++jj) mt = fmaxf(mt, sa[i][jj]);
#pragma unroll
            for (int o = 1; o < 8; o <<= 1)
                mt = fmaxf(mt, __shfl_xor_sync(0xffffffffu, mt, o));
            float mnew  = fmaxf(m_i[i], mt);
            float alpha = __expf(m_i[i] - mnew);
            float rs = 0.f;
#pragma unroll
            for (int jj = 0; jj < 8; ++jj) {
                float p = __expf(sa[i][jj] - mnew);
                sP[(ty * 4 + i) * PSTR + tx + 8 * jj] = p;
                rs += p;
            }
#pragma unroll
            for (int o = 1; o < 8; o <<= 1)
                rs += __shfl_xor_sync(0xffffffffu, rs, o);
            l_i[i] = l_i[i] * alpha + rs;
            m_i[i] = mnew;
#pragma unroll
            for (int c = 0; c < 16; ++c) acc[i][c] *= alpha;
        }

        __syncthreads();   // sKV(K) reads + sP writes complete
        for (int i = tid; i < BN * 32; i += 128) {
            int r = i >> 5, c4 = (i & 31) << 2;
            *(float4*)&sKV[r * QSTR + c4] =
                *(const float4*)&Vb[(((size_t)b * S_ + k0 + r) * KVH_ + hk) * HD_ + c4];
        }
        __syncthreads();

        // O += P V (per-thread 4 rows x 16 d-cols: d = tx*4 + 32*kk + c)
#pragma unroll 4
        for (int n = 0; n < BN; ++n) {
            float p[4];
#pragma unroll
            for (int i = 0; i < 4; ++i) p[i] = sP[(ty * 4 + i) * PSTR + n];
            float4 v[4];
#pragma unroll
            for (int kk = 0; kk < 4; ++kk)
                v[kk] = *(const float4*)&sKV[n * QSTR + tx * 4 + 32 * kk];
#pragma unroll
            for (int i = 0; i < 4; ++i)
#pragma unroll
                for (int kk = 0; kk < 4; ++kk) {
                    acc[i][kk * 4 + 0] += p[i] * v[kk].x;
                    acc[i][kk * 4 + 1] += p[i] * v[kk].y;
                    acc[i][kk * 4 + 2] += p[i] * v[kk].z;
                    acc[i][kk * 4 + 3] += p[i] * v[kk].w;
                }
        }
    }

    // epilogue
#pragma unroll
    for (int i = 0; i < 4; ++i) {
        float inv = 1.f / l_i[i];
        int r = q0 + ty * 4 + i;
#pragma unroll
        for (int kk = 0; kk < 4; ++kk) {
            float4 o;
            o.x = acc[i][kk * 4 + 0] * inv;
            o.y = acc[i][kk * 4 + 1] * inv;
            o.z = acc[i][kk * 4 + 2] * inv;
            o.w = acc[i][kk * 4 + 3] * inv;
            *(float4*)&O[(((size_t)b * S_ + r) * H_ + h) * HD_ + tx * 4 + 32 * kk] = o;
        }
    }
}

// ---------------- host ----------------
extern "C" void kernel_launch(void* const* d_in, const int* in_sizes, int n_in,
                              void* d_out, int out_size) {
    const float* x       = (const float*)d_in[0];
    const float* wq      = (const float*)d_in[1];
    const float* wk      = (const float*)d_in[2];
    const float* wv      = (const float*)d_in[3];
    const float* wo      = (const float*)d_in[4];
    const float* pos_cos = (const float*)d_in[5];
    const float* pos_sin = (const float*)d_in[6];
    float* out = (float*)d_out;

    float *q, *k, *v, *att;
    cudaGetSymbolAddress((void**)&q,   g_q);
    cudaGetSymbolAddress((void**)&k,   g_k);
    cudaGetSymbolAddress((void**)&v,   g_v);
    cudaGetSymbolAddress((void**)&att, g_att);

    const int M = B_ * S_;  // 8192

    // QKV projections
    sgemm128<<<dim3(D_ / 128, M / 128), 256>>>(x, wq, q, M, D_, D_);
    sgemm128<<<dim3((KVH_ * HD_) / 128, M / 128), 256>>>(x, wk, k, M, KVH_ * HD_, D_);
    sgemm128<<<dim3((KVH_ * HD_) / 128, M / 128), 256>>>(x, wv, v, M, KVH_ * HD_, D_);

    // RoPE on q and k
    {
        int np_q = B_ * S_ * H_ * (HD_ / 2);
        int np_k = B_ * S_ * KVH_ * (HD_ / 2);
        rope_kernel<<<(np_q + 255) / 256, 256>>>(q, pos_cos, pos_sin, H_, np_q);
        rope_kernel<<<(np_k + 255) / 256, 256>>>(k, pos_cos, pos_sin, KVH_, np_k);
    }

    // flash attention
    {
        const int smem_bytes = (2 * 64 * QSTR + 64 * PSTR) * (int)sizeof(float); // 84992
        cudaFuncSetAttribute(flash_kernel, cudaFuncAttributeMaxDynamicSharedMemorySize, smem_bytes);
        flash_kernel<<<dim3(S_ / BM, H_, B_), 128, smem_bytes>>>(q, k, v, att);
    }

    // output projection -> d_out
    sgemm128<<<dim3(D_ / 128, M / 128), 256>>>(att, wo, out, M, D_, D_);
}

// round 4
// speedup vs baseline: 1.6705x; 1.6705x over previous
#include <cuda_runtime.h>
#include <cuda_bf16.h>
#include <math.h>
#include <stdint.h>

#define B_   4
#define S_   2048
#define D_   2048
#define H_   16
#define KVH_ 8
#define HD_  128
#define MSZ  (B_ * S_)          // 8192

// ---------------- scratch (device globals; no allocation allowed) ----------------
__device__ float g_q[(size_t)MSZ * D_];                 // 64 MB
__device__ float g_k[(size_t)MSZ * KVH_ * HD_];         // 32 MB
__device__ float g_v[(size_t)MSZ * KVH_ * HD_];         // 32 MB
__device__ float g_att[(size_t)MSZ * D_];               // 64 MB

__device__ __nv_bfloat16 g_xhi[(size_t)MSZ * D_];
__device__ __nv_bfloat16 g_xlo[(size_t)MSZ * D_];
__device__ __nv_bfloat16 g_wqh[(size_t)D_ * D_];
__device__ __nv_bfloat16 g_wql[(size_t)D_ * D_];
__device__ __nv_bfloat16 g_wkh[(size_t)D_ * KVH_ * HD_];
__device__ __nv_bfloat16 g_wkl[(size_t)D_ * KVH_ * HD_];
__device__ __nv_bfloat16 g_wvh[(size_t)D_ * KVH_ * HD_];
__device__ __nv_bfloat16 g_wvl[(size_t)D_ * KVH_ * HD_];
__device__ __nv_bfloat16 g_woh[(size_t)D_ * D_];
__device__ __nv_bfloat16 g_wol[(size_t)D_ * D_];
__device__ __nv_bfloat16 g_athi[(size_t)MSZ * D_];
__device__ __nv_bfloat16 g_atlo[(size_t)MSZ * D_];

// ================= helpers (baseline PTX only; no 'a'-variant features) =================
__device__ __forceinline__ uint32_t smem_u32(const void* p) {
    uint32_t a;
    asm("{ .reg .u64 t; cvta.to.shared.u64 t, %1; cvt.u32.u64 %0, t; }" : "=r"(a) : "l"(p));
    return a;
}
__device__ __forceinline__ void cp_async16(uint32_t dst, const void* src) {
    asm volatile("cp.async.cg.shared.global [%0], [%1], 16;" :: "r"(dst), "l"(src) : "memory");
}
__device__ __forceinline__ void ldmatrix_x4(uint32_t* r, uint32_t addr) {
    asm volatile("ldmatrix.sync.aligned.m8n8.x4.shared.b16 {%0,%1,%2,%3}, [%4];"
                 : "=r"(r[0]), "=r"(r[1]), "=r"(r[2]), "=r"(r[3]) : "r"(addr));
}
__device__ __forceinline__ void mma_bf16(float* c, const uint32_t* a, uint32_t b0, uint32_t b1) {
    asm volatile("mma.sync.aligned.m16n8k16.row.col.f32.bf16.bf16.f32 "
                 "{%0,%1,%2,%3}, {%4,%5,%6,%7}, {%8,%9}, {%0,%1,%2,%3};"
                 : "+f"(c[0]), "+f"(c[1]), "+f"(c[2]), "+f"(c[3])
                 : "r"(a[0]), "r"(a[1]), "r"(a[2]), "r"(a[3]), "r"(b0), "r"(b1));
}

// ================= mma.sync GEMM: C[M,N] = (Ahi+Alo)·(Bhi+Blo)^T (3-pass split-bf16) =================
// A: [M,K] bf16 row-major hi/lo; B: [N,K] bf16 row-major hi/lo (weights pre-transposed).
// CTA 128x128, K-chunk 32, 256 threads (8 warps, each 32x64), double-buffered cp.async.
// smem tile layout: 128 rows x 40 halves (32 data + 8 pad) -> 80B row stride (conflict-free ldmatrix).
#define TILE_H   5120          // halves per tile (128*40)
#define TILE_B   10240         // bytes per tile
#define STAGE_B  40960         // bytes per stage (4 tiles)
#define GEMM_SMEM (2 * STAGE_B)

__global__ __launch_bounds__(256) void gemm_mma(const __nv_bfloat16* __restrict__ Ahi,
                                                const __nv_bfloat16* __restrict__ Alo,
                                                const __nv_bfloat16* __restrict__ Bhi,
                                                const __nv_bfloat16* __restrict__ Blo,
                                                float* __restrict__ C,
                                                int M, int N, int K) {
    extern __shared__ __align__(128) __nv_bfloat16 smh[];
    const int tid = threadIdx.x, lane = tid & 31, wid = tid >> 5;
    const int m0 = blockIdx.y * 128, n0 = blockIdx.x * 128;
    const int wm = (wid & 3) * 32, wn = (wid >> 2) * 64;
    const uint32_t sb = smem_u32(smh);

    const __nv_bfloat16* gsrc[4];
    gsrc[0] = Ahi + (size_t)m0 * K;
    gsrc[1] = Alo + (size_t)m0 * K;
    gsrc[2] = Bhi + (size_t)n0 * K;
    gsrc[3] = Blo + (size_t)n0 * K;

    auto load_chunk = [&](int c, int s) {
        const uint32_t st = sb + s * STAGE_B;
#pragma unroll
        for (int t = 0; t < 8; ++t) {
            int idx = t * 256 + tid;              // 0..2047
            int tile = idx >> 9;                  // 0..3
            int r = (idx >> 2) & 127;             // row
            int seg = idx & 3;                    // 16B segment
            uint32_t dst = st + tile * TILE_B + r * 80 + seg * 16;
            cp_async16(dst, gsrc[tile] + (size_t)r * K + c * 32 + seg * 8);
        }
        asm volatile("cp.async.commit_group;" ::: "memory");
    };

    float acc[2][8][4];
#pragma unroll
    for (int mf = 0; mf < 2; ++mf)
#pragma unroll
        for (int nf = 0; nf < 8; ++nf)
#pragma unroll
            for (int e = 0; e < 4; ++e) acc[mf][nf][e] = 0.f;

    const int nch = K / 32;
    load_chunk(0, 0);
    load_chunk(1, 1);

    for (int i = 0; i < nch; ++i) {
        const int s = i & 1;
        if (i + 1 < nch) asm volatile("cp.async.wait_group 1;" ::: "memory");
        else             asm volatile("cp.async.wait_group 0;" ::: "memory");
        __syncthreads();

        const uint32_t st = sb + s * STAGE_B;
#pragma unroll
        for (int k16 = 0; k16 < 2; ++k16) {
            uint32_t ah[2][4], al[2][4];
#pragma unroll
            for (int mf = 0; mf < 2; ++mf) {
                int rowA = wm + mf * 16 + (lane & 15);
                int kA = k16 * 16 + ((lane >> 4) << 3);
                uint32_t off = (uint32_t)(rowA * 80 + kA * 2);
                ldmatrix_x4(ah[mf], st + off);
                ldmatrix_x4(al[mf], st + TILE_B + off);
            }
            uint32_t bh[4][4], bl[4][4];
#pragma unroll
            for (int nf2 = 0; nf2 < 4; ++nf2) {
                int rowB = wn + nf2 * 16 + (lane & 7) + ((lane >> 4) << 3);
                int kB = k16 * 16 + (((lane >> 3) & 1) << 3);
                uint32_t off = (uint32_t)(rowB * 80 + kB * 2);
                ldmatrix_x4(bh[nf2], st + 2 * TILE_B + off);
                ldmatrix_x4(bl[nf2], st + 3 * TILE_B + off);
            }
#pragma unroll
            for (int mf = 0; mf < 2; ++mf)
#pragma unroll
                for (int nf = 0; nf < 8; ++nf) {
                    uint32_t b0h = bh[nf >> 1][(nf & 1) * 2], b1h = bh[nf >> 1][(nf & 1) * 2 + 1];
                    uint32_t b0l = bl[nf >> 1][(nf & 1) * 2], b1l = bl[nf >> 1][(nf & 1) * 2 + 1];
                    mma_bf16(acc[mf][nf], ah[mf], b0h, b1h);
                    mma_bf16(acc[mf][nf], ah[mf], b0l, b1l);
                    mma_bf16(acc[mf][nf], al[mf], b0h, b1h);
                }
        }
        __syncthreads();
        if (i + 2 < nch) load_chunk(i + 2, s);
    }

    // epilogue: c0,c1 -> (row=t/4, col=(t%4)*2), c2,c3 -> row+8
#pragma unroll
    for (int mf = 0; mf < 2; ++mf) {
        int row = m0 + wm + mf * 16 + (lane >> 2);
#pragma unroll
        for (int nf = 0; nf < 8; ++nf) {
            int col = n0 + wn + nf * 8 + (lane & 3) * 2;
            *(float2*)&C[(size_t)row * N + col] = make_float2(acc[mf][nf][0], acc[mf][nf][1]);
            *(float2*)&C[(size_t)(row + 8) * N + col] = make_float2(acc[mf][nf][2], acc[mf][nf][3]);
        }
    }
}

// ================= fp32 -> bf16 hi/lo split (elementwise) =================
__global__ __launch_bounds__(256) void split_kernel(const float* __restrict__ v,
                                                    __nv_bfloat16* __restrict__ hi,
                                                    __nv_bfloat16* __restrict__ lo,
                                                    size_t n) {
    size_t i = (size_t)blockIdx.x * blockDim.x + threadIdx.x;
    if (i >= n) return;
    float f = v[i];
    __nv_bfloat16 h = __float2bfloat16(f);
    hi[i] = h;
    lo[i] = __float2bfloat16(f - __bfloat162float(h));
}

// ================= weight transpose + split: W[K,N] fp32 -> Wt[N,K] bf16 hi/lo =================
__global__ __launch_bounds__(256) void wsplit_t_kernel(const float* __restrict__ W,
                                                       __nv_bfloat16* __restrict__ hi,
                                                       __nv_bfloat16* __restrict__ lo,
                                                       int Kd, int Nd) {
    __shared__ float t[32][33];
    int k0 = blockIdx.y * 32, n0 = blockIdx.x * 32;
    int x = threadIdx.x, y = threadIdx.y;   // block (32, 8)
#pragma unroll
    for (int i = 0; i < 32; i += 8)
        t[y + i][x] = W[(size_t)(k0 + y + i) * Nd + n0 + x];
    __syncthreads();
#pragma unroll
    for (int i = 0; i < 32; i += 8) {
        float f = t[x][y + i];              // = W[k0+x][n0+y+i]
        __nv_bfloat16 h = __float2bfloat16(f);
        size_t o = (size_t)(n0 + y + i) * Kd + k0 + x;
        hi[o] = h;
        lo[o] = __float2bfloat16(f - __bfloat162float(h));
    }
}

// ---------------- RoPE (in-place), t: [B, S, nh, HD], pairs interleaved ----------------
__global__ __launch_bounds__(256) void rope_kernel(float* __restrict__ t,
                                                   const float* __restrict__ co,
                                                   const float* __restrict__ si,
                                                   int nh, int npairs) {
    int idx = blockIdx.x * blockDim.x + threadIdx.x;
    if (idx >= npairs) return;
    int i = idx & 63;
    int s = ((idx >> 6) / nh) % S_;
    float c  = co[s * 64 + i];
    float sn = si[s * 64 + i];
    float2 v = *(float2*)&t[(size_t)idx * 2];
    float2 o;
    o.x = v.x * c - v.y * sn;
    o.y = v.x * sn + v.y * c;
    *(float2*)&t[(size_t)idx * 2] = o;
}

// ---------------- flash attention (fp32), causal, GQA ----------------
#define BM 64
#define BN 64
#define QSTR 132
#define PSTR 68

__global__ __launch_bounds__(128) void flash_kernel(const float* __restrict__ Q,
                                                    const float* __restrict__ Kb,
                                                    const float* __restrict__ Vb,
                                                    float* __restrict__ O) {
    extern __shared__ float smf[];
    float* sQ  = smf;
    float* sKV = smf + 64 * QSTR;
    float* sP  = smf + 2 * 64 * QSTR;

    const int qt = blockIdx.x;
    const int h  = blockIdx.y;
    const int b  = blockIdx.z;
    const int hk = h >> 1;
    const int tid = threadIdx.x;
    const int tx = tid & 7;
    const int ty = tid >> 3;
    const int q0 = qt * BM;
    const float scale = 0.08838834764831845f;

    for (int i = tid; i < BM * 32; i += 128) {
        int r = i >> 5, c4 = (i & 31) << 2;
        float4 v = *(const float4*)&Q[(((size_t)b * S_ + q0 + r) * H_ + h) * HD_ + c4];
        v.x *= scale; v.y *= scale; v.z *= scale; v.w *= scale;
        *(float4*)&sQ[r * QSTR + c4] = v;
    }

    float m_i[4], l_i[4], acc[4][16];
#pragma unroll
    for (int i = 0; i < 4; ++i) {
        m_i[i] = -1e30f; l_i[i] = 0.f;
#pragma unroll
        for (int c = 0; c < 16; ++c) acc[i][c] = 0.f;
    }

    for (int j = 0; j <= qt; ++j) {
        const int k0 = j * BN;

        __syncthreads();
        for (int i = tid; i < BN * 32; i += 128) {
            int r = i >> 5, c4 = (i & 31) << 2;
            *(float4*)&sKV[r * QSTR + c4] =
                *(const float4*)&Kb[(((size_t)b * S_ + k0 + r) * KVH_ + hk) * HD_ + c4];
        }
        __syncthreads();

        float sa[4][8];
#pragma unroll
        for (int i = 0; i < 4; ++i)
#pragma unroll
            for (int jj = 0; jj < 8; ++jj) sa[i][jj] = 0.f;

#pragma unroll 2
        for (int d = 0; d < HD_; d += 4) {
            float4 qv[4], kv[8];
#pragma unroll
            for (int i = 0; i < 4; ++i)
                qv[i] = *(const float4*)&sQ[(ty * 4 + i) * QSTR + d];
#pragma unroll
            for (int jj = 0; jj < 8; ++jj)
                kv[jj] = *(const float4*)&sKV[(tx + 8 * jj) * QSTR + d];
#pragma unroll
            for (int i = 0; i < 4; ++i)
#pragma unroll
                for (int jj = 0; jj < 8; ++jj) {
                    sa[i][jj] += qv[i].x * kv[jj].x;
                    sa[i][jj] += qv[i].y * kv[jj].y;
                    sa[i][jj] += qv[i].z * kv[jj].z;
                    sa[i][jj] += qv[i].w * kv[jj].w;
                }
        }

        if (j == qt) {
#pragma unroll
            for (int i = 0; i < 4; ++i)
#pragma unroll
                for (int jj = 0; jj < 8; ++jj)
                    if (tx + 8 * jj > ty * 4 + i) sa[i][jj] = -1e30f;
        }

#pragma unroll
        for (int i = 0; i < 4; ++i) {
            float mt = sa[i][0];
#pragma unroll
            for (int jj = 1; jj < 8; ++jj) mt = fmaxf(mt, sa[i][jj]);
#pragma unroll
            for (int o = 1; o < 8; o <<= 1)
                mt = fmaxf(mt, __shfl_xor_sync(0xffffffffu, mt, o));
            float mnew  = fmaxf(m_i[i], mt);
            float alpha = __expf(m_i[i] - mnew);
            float rs = 0.f;
#pragma unroll
            for (int jj = 0; jj < 8; ++jj) {
                float p = __expf(sa[i][jj] - mnew);
                sP[(ty * 4 + i) * PSTR + tx + 8 * jj] = p;
                rs += p;
            }
#pragma unroll
            for (int o = 1; o < 8; o <<= 1)
                rs += __shfl_xor_sync(0xffffffffu, rs, o);
            l_i[i] = l_i[i] * alpha + rs;
            m_i[i] = mnew;
#pragma unroll
            for (int c = 0; c < 16; ++c) acc[i][c] *= alpha;
        }

        __syncthreads();
        for (int i = tid; i < BN * 32; i += 128) {
            int r = i >> 5, c4 = (i & 31) << 2;
            *(float4*)&sKV[r * QSTR + c4] =
                *(const float4*)&Vb[(((size_t)b * S_ + k0 + r) * KVH_ + hk) * HD_ + c4];
        }
        __syncthreads();

#pragma unroll 4
        for (int n = 0; n < BN; ++n) {
            float p[4];
#pragma unroll
            for (int i = 0; i < 4; ++i) p[i] = sP[(ty * 4 + i) * PSTR + n];
            float4 v[4];
#pragma unroll
            for (int kk = 0; kk < 4; ++kk)
                v[kk] = *(const float4*)&sKV[n * QSTR + tx * 4 + 32 * kk];
#pragma unroll
            for (int i = 0; i < 4; ++i)
#pragma unroll
                for (int kk = 0; kk < 4; ++kk) {
                    acc[i][kk * 4 + 0] += p[i] * v[kk].x;
                    acc[i][kk * 4 + 1] += p[i] * v[kk].y;
                    acc[i][kk * 4 + 2] += p[i] * v[kk].z;
                    acc[i][kk * 4 + 3] += p[i] * v[kk].w;
                }
        }
    }

#pragma unroll
    for (int i = 0; i < 4; ++i) {
        float inv = 1.f / l_i[i];
        int r = q0 + ty * 4 + i;
#pragma unroll
        for (int kk = 0; kk < 4; ++kk) {
            float4 o;
            o.x = acc[i][kk * 4 + 0] * inv;
            o.y = acc[i][kk * 4 + 1] * inv;
            o.z = acc[i][kk * 4 + 2] * inv;
            o.w = acc[i][kk * 4 + 3] * inv;
            *(float4*)&O[(((size_t)b * S_ + r) * H_ + h) * HD_ + tx * 4 + 32 * kk] = o;
        }
    }
}

// ---------------- host ----------------
extern "C" void kernel_launch(void* const* d_in, const int* in_sizes, int n_in,
                              void* d_out, int out_size) {
    const float* x       = (const float*)d_in[0];
    const float* wq      = (const float*)d_in[1];
    const float* wk      = (const float*)d_in[2];
    const float* wv      = (const float*)d_in[3];
    const float* wo      = (const float*)d_in[4];
    const float* pos_cos = (const float*)d_in[5];
    const float* pos_sin = (const float*)d_in[6];
    float* out = (float*)d_out;

    float *q, *k, *v, *att;
    cudaGetSymbolAddress((void**)&q,   g_q);
    cudaGetSymbolAddress((void**)&k,   g_k);
    cudaGetSymbolAddress((void**)&v,   g_v);
    cudaGetSymbolAddress((void**)&att, g_att);
    __nv_bfloat16 *xhi, *xlo, *wqh, *wql, *wkh, *wkl, *wvh, *wvl, *woh, *wol, *athi, *atlo;
    cudaGetSymbolAddress((void**)&xhi, g_xhi);  cudaGetSymbolAddress((void**)&xlo, g_xlo);
    cudaGetSymbolAddress((void**)&wqh, g_wqh);  cudaGetSymbolAddress((void**)&wql, g_wql);
    cudaGetSymbolAddress((void**)&wkh, g_wkh);  cudaGetSymbolAddress((void**)&wkl, g_wkl);
    cudaGetSymbolAddress((void**)&wvh, g_wvh);  cudaGetSymbolAddress((void**)&wvl, g_wvl);
    cudaGetSymbolAddress((void**)&woh, g_woh);  cudaGetSymbolAddress((void**)&wol, g_wol);
    cudaGetSymbolAddress((void**)&athi, g_athi); cudaGetSymbolAddress((void**)&atlo, g_atlo);

    const int M = MSZ;          // 8192
    const int KV = KVH_ * HD_;  // 1024

    // input/weight conversions
    {
        size_t nx = (size_t)M * D_;
        split_kernel<<<(unsigned)((nx + 255) / 256), 256>>>(x, xhi, xlo, nx);
        wsplit_t_kernel<<<dim3(D_ / 32, D_ / 32), dim3(32, 8)>>>(wq, wqh, wql, D_, D_);
        wsplit_t_kernel<<<dim3(KV / 32, D_ / 32), dim3(32, 8)>>>(wk, wkh, wkl, D_, KV);
        wsplit_t_kernel<<<dim3(KV / 32, D_ / 32), dim3(32, 8)>>>(wv, wvh, wvl, D_, KV);
        wsplit_t_kernel<<<dim3(D_ / 32, D_ / 32), dim3(32, 8)>>>(wo, woh, wol, D_, D_);
    }

    cudaFuncSetAttribute(gemm_mma, cudaFuncAttributeMaxDynamicSharedMemorySize, GEMM_SMEM);

    // QKV projections (mma.sync bf16, 3-pass split)
    gemm_mma<<<dim3(D_ / 128, M / 128), 256, GEMM_SMEM>>>(xhi, xlo, wqh, wql, q, M, D_, D_);
    gemm_mma<<<dim3(KV / 128, M / 128), 256, GEMM_SMEM>>>(xhi, xlo, wkh, wkl, k, M, KV, D_);
    gemm_mma<<<dim3(KV / 128, M / 128), 256, GEMM_SMEM>>>(xhi, xlo, wvh, wvl, v, M, KV, D_);

    // RoPE on q and k
    {
        int np_q = B_ * S_ * H_ * (HD_ / 2);
        int np_k = B_ * S_ * KVH_ * (HD_ / 2);
        rope_kernel<<<(np_q + 255) / 256, 256>>>(q, pos_cos, pos_sin, H_, np_q);
        rope_kernel<<<(np_k + 255) / 256, 256>>>(k, pos_cos, pos_sin, KVH_, np_k);
    }

    // flash attention
    {
        const int smem_bytes = (2 * 64 * QSTR + 64 * PSTR) * (int)sizeof(float);
        cudaFuncSetAttribute(flash_kernel, cudaFuncAttributeMaxDynamicSharedMemorySize, smem_bytes);
        flash_kernel<<<dim3(S_ / BM, H_, B_), 128, smem_bytes>>>(q, k, v, att);
    }

    // attention output conversion + output projection -> d_out
    {
        size_t na = (size_t)M * D_;
        split_kernel<<<(unsigned)((na + 255) / 256), 256>>>(att, athi, atlo, na);
        gemm_mma<<<dim3(D_ / 128, M / 128), 256, GEMM_SMEM>>>(athi, atlo, woh, wol, out, M, D_, D_);
    }
}

// round 5
// speedup vs baseline: 2.6137x; 1.5646x over previous
#include <cuda_runtime.h>
#include <cuda_bf16.h>
#include <math.h>
#include <stdint.h>

#define B_   4
#define S_   2048
#define D_   2048
#define H_   16
#define KVH_ 8
#define HD_  128
#define MSZ  (B_ * S_)          // 8192

// ---------------- scratch (device globals; no allocation allowed) ----------------
__device__ float g_q[(size_t)MSZ * D_];                 // fp32 q after proj
__device__ float g_k[(size_t)MSZ * KVH_ * HD_];
__device__ float g_v[(size_t)MSZ * KVH_ * HD_];

__device__ __nv_bfloat16 g_xhi[(size_t)MSZ * D_];
__device__ __nv_bfloat16 g_xlo[(size_t)MSZ * D_];
__device__ __nv_bfloat16 g_wqh[(size_t)D_ * D_];
__device__ __nv_bfloat16 g_wql[(size_t)D_ * D_];
__device__ __nv_bfloat16 g_wkh[(size_t)D_ * KVH_ * HD_];
__device__ __nv_bfloat16 g_wkl[(size_t)D_ * KVH_ * HD_];
__device__ __nv_bfloat16 g_wvh[(size_t)D_ * KVH_ * HD_];
__device__ __nv_bfloat16 g_wvl[(size_t)D_ * KVH_ * HD_];
__device__ __nv_bfloat16 g_woh[(size_t)D_ * D_];
__device__ __nv_bfloat16 g_wol[(size_t)D_ * D_];
__device__ __nv_bfloat16 g_athi[(size_t)MSZ * D_];
__device__ __nv_bfloat16 g_atlo[(size_t)MSZ * D_];

// flash operands (bf16 splits)
__device__ __nv_bfloat16 g_qhi[(size_t)MSZ * D_];
__device__ __nv_bfloat16 g_qlo[(size_t)MSZ * D_];
__device__ __nv_bfloat16 g_khi[(size_t)MSZ * KVH_ * HD_];
__device__ __nv_bfloat16 g_klo[(size_t)MSZ * KVH_ * HD_];
__device__ __nv_bfloat16 g_vthi[(size_t)MSZ * KVH_ * HD_];   // [b][hk][d][s]
__device__ __nv_bfloat16 g_vtlo[(size_t)MSZ * KVH_ * HD_];

// ================= helpers (baseline PTX only) =================
__device__ __forceinline__ uint32_t smem_u32(const void* p) {
    uint32_t a;
    asm("{ .reg .u64 t; cvta.to.shared.u64 t, %1; cvt.u32.u64 %0, t; }" : "=r"(a) : "l"(p));
    return a;
}
__device__ __forceinline__ void cp_async16(uint32_t dst, const void* src) {
    asm volatile("cp.async.cg.shared.global [%0], [%1], 16;" :: "r"(dst), "l"(src) : "memory");
}
__device__ __forceinline__ void ldmatrix_x4(uint32_t* r, uint32_t addr) {
    asm volatile("ldmatrix.sync.aligned.m8n8.x4.shared.b16 {%0,%1,%2,%3}, [%4];"
                 : "=r"(r[0]), "=r"(r[1]), "=r"(r[2]), "=r"(r[3]) : "r"(addr));
}
__device__ __forceinline__ void mma_bf16(float* c, const uint32_t* a, uint32_t b0, uint32_t b1) {
    asm volatile("mma.sync.aligned.m16n8k16.row.col.f32.bf16.bf16.f32 "
                 "{%0,%1,%2,%3}, {%4,%5,%6,%7}, {%8,%9}, {%0,%1,%2,%3};"
                 : "+f"(c[0]), "+f"(c[1]), "+f"(c[2]), "+f"(c[3])
                 : "r"(a[0]), "r"(a[1]), "r"(a[2]), "r"(a[3]), "r"(b0), "r"(b1));
}
__device__ __forceinline__ void split_pack(float f0, float f1, uint32_t& hi, uint32_t& lo) {
    __nv_bfloat16 h0 = __float2bfloat16(f0), h1 = __float2bfloat16(f1);
    __nv_bfloat16 l0 = __float2bfloat16(f0 - __bfloat162float(h0));
    __nv_bfloat16 l1 = __float2bfloat16(f1 - __bfloat162float(h1));
    __nv_bfloat162 Hv = __halves2bfloat162(h0, h1);
    __nv_bfloat162 Lv = __halves2bfloat162(l0, l1);
    hi = *(uint32_t*)&Hv; lo = *(uint32_t*)&Lv;
}
__device__ __forceinline__ void store_split2(__nv_bfloat16* hi, __nv_bfloat16* lo,
                                             size_t off, float f0, float f1) {
    __nv_bfloat16 h0 = __float2bfloat16(f0), h1 = __float2bfloat16(f1);
    *(__nv_bfloat162*)(hi + off) = __halves2bfloat162(h0, h1);
    *(__nv_bfloat162*)(lo + off) = __halves2bfloat162(
        __float2bfloat16(f0 - __bfloat162float(h0)),
        __float2bfloat16(f1 - __bfloat162float(h1)));
}

// ================= mma.sync GEMM (unchanged from R4, proven) =================
#define TILE_H   5120
#define TILE_B   10240
#define STAGE_B  40960
#define GEMM_SMEM (2 * STAGE_B)

__global__ __launch_bounds__(256) void gemm_mma(const __nv_bfloat16* __restrict__ Ahi,
                                                const __nv_bfloat16* __restrict__ Alo,
                                                const __nv_bfloat16* __restrict__ Bhi,
                                                const __nv_bfloat16* __restrict__ Blo,
                                                float* __restrict__ C,
                                                int M, int N, int K) {
    extern __shared__ __align__(128) __nv_bfloat16 smh[];
    const int tid = threadIdx.x, lane = tid & 31, wid = tid >> 5;
    const int m0 = blockIdx.y * 128, n0 = blockIdx.x * 128;
    const int wm = (wid & 3) * 32, wn = (wid >> 2) * 64;
    const uint32_t sb = smem_u32(smh);

    const __nv_bfloat16* gsrc[4];
    gsrc[0] = Ahi + (size_t)m0 * K;
    gsrc[1] = Alo + (size_t)m0 * K;
    gsrc[2] = Bhi + (size_t)n0 * K;
    gsrc[3] = Blo + (size_t)n0 * K;

    auto load_chunk = [&](int c, int s) {
        const uint32_t st = sb + s * STAGE_B;
#pragma unroll
        for (int t = 0; t < 8; ++t) {
            int idx = t * 256 + tid;
            int tile = idx >> 9;
            int r = (idx >> 2) & 127;
            int seg = idx & 3;
            uint32_t dst = st + tile * TILE_B + r * 80 + seg * 16;
            cp_async16(dst, gsrc[tile] + (size_t)r * K + c * 32 + seg * 8);
        }
        asm volatile("cp.async.commit_group;" ::: "memory");
    };

    float acc[2][8][4];
#pragma unroll
    for (int mf = 0; mf < 2; ++mf)
#pragma unroll
        for (int nf = 0; nf < 8; ++nf)
#pragma unroll
            for (int e = 0; e < 4; ++e) acc[mf][nf][e] = 0.f;

    const int nch = K / 32;
    load_chunk(0, 0);
    load_chunk(1, 1);

    for (int i = 0; i < nch; ++i) {
        const int s = i & 1;
        if (i + 1 < nch) asm volatile("cp.async.wait_group 1;" ::: "memory");
        else             asm volatile("cp.async.wait_group 0;" ::: "memory");
        __syncthreads();

        const uint32_t st = sb + s * STAGE_B;
#pragma unroll
        for (int k16 = 0; k16 < 2; ++k16) {
            uint32_t ah[2][4], al[2][4];
#pragma unroll
            for (int mf = 0; mf < 2; ++mf) {
                int rowA = wm + mf * 16 + (lane & 15);
                int kA = k16 * 16 + ((lane >> 4) << 3);
                uint32_t off = (uint32_t)(rowA * 80 + kA * 2);
                ldmatrix_x4(ah[mf], st + off);
                ldmatrix_x4(al[mf], st + TILE_B + off);
            }
            uint32_t bh[4][4], bl[4][4];
#pragma unroll
            for (int nf2 = 0; nf2 < 4; ++nf2) {
                int rowB = wn + nf2 * 16 + (lane & 7) + ((lane >> 4) << 3);
                int kB = k16 * 16 + (((lane >> 3) & 1) << 3);
                uint32_t off = (uint32_t)(rowB * 80 + kB * 2);
                ldmatrix_x4(bh[nf2], st + 2 * TILE_B + off);
                ldmatrix_x4(bl[nf2], st + 3 * TILE_B + off);
            }
#pragma unroll
            for (int mf = 0; mf < 2; ++mf)
#pragma unroll
                for (int nf = 0; nf < 8; ++nf) {
                    uint32_t b0h = bh[nf >> 1][(nf & 1) * 2], b1h = bh[nf >> 1][(nf & 1) * 2 + 1];
                    uint32_t b0l = bl[nf >> 1][(nf & 1) * 2], b1l = bl[nf >> 1][(nf & 1) * 2 + 1];
                    mma_bf16(acc[mf][nf], ah[mf], b0h, b1h);
                    mma_bf16(acc[mf][nf], ah[mf], b0l, b1l);
                    mma_bf16(acc[mf][nf], al[mf], b0h, b1h);
                }
        }
        __syncthreads();
        if (i + 2 < nch) load_chunk(i + 2, s);
    }

#pragma unroll
    for (int mf = 0; mf < 2; ++mf) {
        int row = m0 + wm + mf * 16 + (lane >> 2);
#pragma unroll
        for (int nf = 0; nf < 8; ++nf) {
            int col = n0 + wn + nf * 8 + (lane & 3) * 2;
            *(float2*)&C[(size_t)row * N + col] = make_float2(acc[mf][nf][0], acc[mf][nf][1]);
            *(float2*)&C[(size_t)(row + 8) * N + col] = make_float2(acc[mf][nf][2], acc[mf][nf][3]);
        }
    }
}

// ================= fp32 -> bf16 hi/lo split (elementwise) =================
__global__ __launch_bounds__(256) void split_kernel(const float* __restrict__ v,
                                                    __nv_bfloat16* __restrict__ hi,
                                                    __nv_bfloat16* __restrict__ lo,
                                                    size_t n) {
    size_t i = (size_t)blockIdx.x * blockDim.x + threadIdx.x;
    if (i >= n) return;
    float f = v[i];
    __nv_bfloat16 h = __float2bfloat16(f);
    hi[i] = h;
    lo[i] = __float2bfloat16(f - __bfloat162float(h));
}

// ================= weight transpose + split =================
__global__ __launch_bounds__(256) void wsplit_t_kernel(const float* __restrict__ W,
                                                       __nv_bfloat16* __restrict__ hi,
                                                       __nv_bfloat16* __restrict__ lo,
                                                       int Kd, int Nd) {
    __shared__ float t[32][33];
    int k0 = blockIdx.y * 32, n0 = blockIdx.x * 32;
    int x = threadIdx.x, y = threadIdx.y;
#pragma unroll
    for (int i = 0; i < 32; i += 8)
        t[y + i][x] = W[(size_t)(k0 + y + i) * Nd + n0 + x];
    __syncthreads();
#pragma unroll
    for (int i = 0; i < 32; i += 8) {
        float f = t[x][y + i];
        __nv_bfloat16 h = __float2bfloat16(f);
        size_t o = (size_t)(n0 + y + i) * Kd + k0 + x;
        hi[o] = h;
        lo[o] = __float2bfloat16(f - __bfloat162float(h));
    }
}

// ================= RoPE + scale + split (fp32 in, bf16 hi/lo out) =================
__global__ __launch_bounds__(256) void rope_split_kernel(const float* __restrict__ t,
                                                         const float* __restrict__ co,
                                                         const float* __restrict__ si,
                                                         __nv_bfloat16* __restrict__ hi,
                                                         __nv_bfloat16* __restrict__ lo,
                                                         int nh, float scale, int npairs) {
    int idx = blockIdx.x * blockDim.x + threadIdx.x;
    if (idx >= npairs) return;
    int i = idx & 63;
    int s = ((idx >> 6) / nh) % S_;
    float c  = co[s * 64 + i];
    float sn = si[s * 64 + i];
    float2 v = *(const float2*)&t[(size_t)idx * 2];
    float o0 = (v.x * c - v.y * sn) * scale;
    float o1 = (v.x * sn + v.y * c) * scale;
    store_split2(hi, lo, (size_t)idx * 2, o0, o1);
}

// ================= V transpose + split: v[b][s][hk][d] -> vt[b][hk][d][s] =================
__global__ __launch_bounds__(256) void vsplit_t_kernel(const float* __restrict__ v,
                                                       __nv_bfloat16* __restrict__ hi,
                                                       __nv_bfloat16* __restrict__ lo) {
    __shared__ float t[32][33];
    int bz = blockIdx.z;            // b*KVH + hk
    int b = bz >> 3, hk = bz & 7;
    int s0 = blockIdx.y * 32, d0 = blockIdx.x * 32;
    int x = threadIdx.x, y = threadIdx.y;
#pragma unroll
    for (int i = 0; i < 32; i += 8)
        t[y + i][x] = v[(((size_t)b * S_ + s0 + y + i) * KVH_ + hk) * HD_ + d0 + x];
    __syncthreads();
#pragma unroll
    for (int i = 0; i < 32; i += 8) {
        float f = t[x][y + i];     // v[s0+x][d0+y+i]
        __nv_bfloat16 h = __float2bfloat16(f);
        size_t o = (((size_t)b * KVH_ + hk) * HD_ + d0 + y + i) * S_ + s0 + x;
        hi[o] = h;
        lo[o] = __float2bfloat16(f - __bfloat162float(h));
    }
}

// ================= flash attention via mma.sync, split-bf16, causal, GQA =================
// CTA: 128 q-rows x one (b,h). 8 warps, 16 rows each. KV tiles of 64, double-buffered.
#define FQ_ST 272               // Q/K smem row stride bytes (136 halves)
#define FV_ST 144               // V^T row stride bytes (72 halves)
#define SQ_SPLIT 34816          // 128*272
#define SK_SPLIT 17408          // 64*272
#define SV_SPLIT 18432          // 128*144
#define FSTAGE (2 * SK_SPLIT + 2 * SV_SPLIT)    // 71680
#define FQ_TOTAL (2 * SQ_SPLIT)                 // 69632
#define FLASH_SMEM (FQ_TOTAL + 2 * FSTAGE)      // 212992

__global__ __launch_bounds__(256) void flash_mma(
    const __nv_bfloat16* __restrict__ qhi, const __nv_bfloat16* __restrict__ qlo,
    const __nv_bfloat16* __restrict__ khi, const __nv_bfloat16* __restrict__ klo,
    const __nv_bfloat16* __restrict__ vthi, const __nv_bfloat16* __restrict__ vtlo,
    __nv_bfloat16* __restrict__ athi, __nv_bfloat16* __restrict__ atlo) {
    extern __shared__ __align__(128) char smc[];
    const uint32_t sb = smem_u32(smc);
    const int tid = threadIdx.x, lane = tid & 31, w = tid >> 5;
    const int qt = blockIdx.x, h = blockIdx.y, b = blockIdx.z, hk = h >> 1;
    const int q0 = qt * 128;
    const int ntiles = 2 * qt + 2;

    // Q load (both splits) — joins tile0's commit group
#pragma unroll
    for (int t = 0; t < 8; ++t) {
        int idx = t * 256 + tid;
        int r = idx >> 4, seg = idx & 15;
        size_t go = (((size_t)b * S_ + q0 + r) * H_ + h) * HD_ + seg * 8;
        uint32_t d = sb + (uint32_t)(r * FQ_ST + seg * 16);
        cp_async16(d, qhi + go);
        cp_async16(d + SQ_SPLIT, qlo + go);
    }

    auto load_tile = [&](int j, int s) {
        const uint32_t stb = sb + FQ_TOTAL + s * FSTAGE;
#pragma unroll
        for (int t = 0; t < 4; ++t) {
            int idx = t * 256 + tid;
            int r = idx >> 4, seg = idx & 15;
            size_t go = (((size_t)b * S_ + j * 64 + r) * KVH_ + hk) * HD_ + seg * 8;
            uint32_t d = stb + (uint32_t)(r * FQ_ST + seg * 16);
            cp_async16(d, khi + go);
            cp_async16(d + SK_SPLIT, klo + go);
        }
#pragma unroll
        for (int t = 0; t < 4; ++t) {
            int idx = t * 256 + tid;
            int dd = idx >> 3, seg = idx & 7;
            size_t go = (((size_t)b * KVH_ + hk) * HD_ + dd) * S_ + j * 64 + seg * 8;
            uint32_t d = stb + 2 * SK_SPLIT + (uint32_t)(dd * FV_ST + seg * 16);
            cp_async16(d, vthi + go);
            cp_async16(d + SV_SPLIT, vtlo + go);
        }
        asm volatile("cp.async.commit_group;" ::: "memory");
    };

    load_tile(0, 0);
    load_tile(1, 1);

    float o[16][4];
#pragma unroll
    for (int nf = 0; nf < 16; ++nf)
#pragma unroll
        for (int e = 0; e < 4; ++e) o[nf][e] = 0.f;
    float mA = -1e30f, mB = -1e30f, lA = 0.f, lB = 0.f;

    for (int i = 0; i < ntiles; ++i) {
        if (i + 1 < ntiles) asm volatile("cp.async.wait_group 1;" ::: "memory");
        else                asm volatile("cp.async.wait_group 0;" ::: "memory");
        __syncthreads();
        const uint32_t st = sb + FQ_TOTAL + (i & 1) * FSTAGE;

        // ---- S = Q K^T (3-pass split) ----
        float c[8][4];
#pragma unroll
        for (int nf = 0; nf < 8; ++nf)
#pragma unroll
            for (int e = 0; e < 4; ++e) c[nf][e] = 0.f;

#pragma unroll
        for (int k16 = 0; k16 < 8; ++k16) {
            uint32_t ah[4], al[4];
            uint32_t offA = (uint32_t)((w * 16 + (lane & 15)) * FQ_ST +
                                       (k16 * 16 + ((lane >> 4) << 3)) * 2);
            ldmatrix_x4(ah, sb + offA);
            ldmatrix_x4(al, sb + SQ_SPLIT + offA);
            uint32_t bh[4][4], bl[4][4];
#pragma unroll
            for (int nf2 = 0; nf2 < 4; ++nf2) {
                uint32_t offB = (uint32_t)((nf2 * 16 + (lane & 7) + ((lane >> 4) << 3)) * FQ_ST +
                                           (k16 * 16 + (((lane >> 3) & 1) << 3)) * 2);
                ldmatrix_x4(bh[nf2], st + offB);
                ldmatrix_x4(bl[nf2], st + SK_SPLIT + offB);
            }
#pragma unroll
            for (int nf = 0; nf < 8; ++nf) {
                uint32_t b0h = bh[nf >> 1][(nf & 1) * 2], b1h = bh[nf >> 1][(nf & 1) * 2 + 1];
                uint32_t b0l = bl[nf >> 1][(nf & 1) * 2], b1l = bl[nf >> 1][(nf & 1) * 2 + 1];
                mma_bf16(c[nf], ah, b0h, b1h);
                mma_bf16(c[nf], ah, b0l, b1l);
                mma_bf16(c[nf], al, b0h, b1h);
            }
        }

        // ---- causal mask (only diagonal tiles) ----
        if (i >= 2 * qt) {
            int rowA = q0 + w * 16 + (lane >> 2);
            int colb = i * 64 + (lane & 3) * 2;
#pragma unroll
            for (int nf = 0; nf < 8; ++nf) {
                int c0 = colb + nf * 8, c1 = c0 + 1;
                if (c0 > rowA) c[nf][0] = -1e30f;
                if (c1 > rowA) c[nf][1] = -1e30f;
                if (c0 > rowA + 8) c[nf][2] = -1e30f;
                if (c1 > rowA + 8) c[nf][3] = -1e30f;
            }
        }

        // ---- online softmax (rows rA = lane>>2, rB = rA+8 within warp block) ----
        float mtA = -1e30f, mtB = -1e30f;
#pragma unroll
        for (int nf = 0; nf < 8; ++nf) {
            mtA = fmaxf(mtA, fmaxf(c[nf][0], c[nf][1]));
            mtB = fmaxf(mtB, fmaxf(c[nf][2], c[nf][3]));
        }
        mtA = fmaxf(mtA, __shfl_xor_sync(0xffffffffu, mtA, 1));
        mtA = fmaxf(mtA, __shfl_xor_sync(0xffffffffu, mtA, 2));
        mtB = fmaxf(mtB, __shfl_xor_sync(0xffffffffu, mtB, 1));
        mtB = fmaxf(mtB, __shfl_xor_sync(0xffffffffu, mtB, 2));
        float mnA = fmaxf(mA, mtA), mnB = fmaxf(mB, mtB);
        float aA = __expf(mA - mnA), aB = __expf(mB - mnB);
        mA = mnA; mB = mnB;
        float rsA = 0.f, rsB = 0.f;
#pragma unroll
        for (int nf = 0; nf < 8; ++nf) {
            c[nf][0] = __expf(c[nf][0] - mnA);
            c[nf][1] = __expf(c[nf][1] - mnA);
            c[nf][2] = __expf(c[nf][2] - mnB);
            c[nf][3] = __expf(c[nf][3] - mnB);
            rsA += c[nf][0] + c[nf][1];
            rsB += c[nf][2] + c[nf][3];
        }
        rsA += __shfl_xor_sync(0xffffffffu, rsA, 1);
        rsA += __shfl_xor_sync(0xffffffffu, rsA, 2);
        rsB += __shfl_xor_sync(0xffffffffu, rsB, 1);
        rsB += __shfl_xor_sync(0xffffffffu, rsB, 2);
        lA = lA * aA + rsA;
        lB = lB * aB + rsB;
#pragma unroll
        for (int nf = 0; nf < 16; ++nf) {
            o[nf][0] *= aA; o[nf][1] *= aA;
            o[nf][2] *= aB; o[nf][3] *= aB;
        }

        // ---- O += P V (3-pass split; P converted C-frag -> A-frag in registers) ----
        const uint32_t stv = st + 2 * SK_SPLIT;
#pragma unroll
        for (int kc = 0; kc < 4; ++kc) {
            uint32_t ph[4], pl[4];
            split_pack(c[2 * kc][0],     c[2 * kc][1],     ph[0], pl[0]);
            split_pack(c[2 * kc][2],     c[2 * kc][3],     ph[1], pl[1]);
            split_pack(c[2 * kc + 1][0], c[2 * kc + 1][1], ph[2], pl[2]);
            split_pack(c[2 * kc + 1][2], c[2 * kc + 1][3], ph[3], pl[3]);
#pragma unroll
            for (int nf2 = 0; nf2 < 8; ++nf2) {
                uint32_t offV = (uint32_t)((nf2 * 16 + (lane & 7) + ((lane >> 4) << 3)) * FV_ST +
                                           (kc * 16 + (((lane >> 3) & 1) << 3)) * 2);
                uint32_t vh[4], vl[4];
                ldmatrix_x4(vh, stv + offV);
                ldmatrix_x4(vl, stv + SV_SPLIT + offV);
#pragma unroll
                for (int t = 0; t < 2; ++t) {
                    int nf = nf2 * 2 + t;
                    mma_bf16(o[nf], ph, vh[t * 2], vh[t * 2 + 1]);
                    mma_bf16(o[nf], ph, vl[t * 2], vl[t * 2 + 1]);
                    mma_bf16(o[nf], pl, vh[t * 2], vh[t * 2 + 1]);
                }
            }
        }
        __syncthreads();
        if (i + 2 < ntiles) load_tile(i + 2, i & 1);
    }

    // ---- epilogue: O/l -> athi/atlo directly ----
    float iA = 1.f / lA, iB = 1.f / lB;
    int rowA = q0 + w * 16 + (lane >> 2);
#pragma unroll
    for (int nf = 0; nf < 16; ++nf) {
        int dcol = nf * 8 + (lane & 3) * 2;
        size_t oA = (((size_t)b * S_ + rowA) * H_ + h) * HD_ + dcol;
        size_t oB = (((size_t)b * S_ + rowA + 8) * H_ + h) * HD_ + dcol;
        store_split2(athi, atlo, oA, o[nf][0] * iA, o[nf][1] * iA);
        store_split2(athi, atlo, oB, o[nf][2] * iB, o[nf][3] * iB);
    }
}

// ---------------- host ----------------
extern "C" void kernel_launch(void* const* d_in, const int* in_sizes, int n_in,
                              void* d_out, int out_size) {
    const float* x       = (const float*)d_in[0];
    const float* wq      = (const float*)d_in[1];
    const float* wk      = (const float*)d_in[2];
    const float* wv      = (const float*)d_in[3];
    const float* wo      = (const float*)d_in[4];
    const float* pos_cos = (const float*)d_in[5];
    const float* pos_sin = (const float*)d_in[6];
    float* out = (float*)d_out;

    float *q, *k, *v;
    cudaGetSymbolAddress((void**)&q, g_q);
    cudaGetSymbolAddress((void**)&k, g_k);
    cudaGetSymbolAddress((void**)&v, g_v);
    __nv_bfloat16 *xhi, *xlo, *wqh, *wql, *wkh, *wkl, *wvh, *wvl, *woh, *wol, *athi, *atlo;
    __nv_bfloat16 *qhi, *qlo, *khi, *klo, *vthi, *vtlo;
    cudaGetSymbolAddress((void**)&xhi, g_xhi);  cudaGetSymbolAddress((void**)&xlo, g_xlo);
    cudaGetSymbolAddress((void**)&wqh, g_wqh);  cudaGetSymbolAddress((void**)&wql, g_wql);
    cudaGetSymbolAddress((void**)&wkh, g_wkh);  cudaGetSymbolAddress((void**)&wkl, g_wkl);
    cudaGetSymbolAddress((void**)&wvh, g_wvh);  cudaGetSymbolAddress((void**)&wvl, g_wvl);
    cudaGetSymbolAddress((void**)&woh, g_woh);  cudaGetSymbolAddress((void**)&wol, g_wol);
    cudaGetSymbolAddress((void**)&athi, g_athi); cudaGetSymbolAddress((void**)&atlo, g_atlo);
    cudaGetSymbolAddress((void**)&qhi, g_qhi);  cudaGetSymbolAddress((void**)&qlo, g_qlo);
    cudaGetSymbolAddress((void**)&khi, g_khi);  cudaGetSymbolAddress((void**)&klo, g_klo);
    cudaGetSymbolAddress((void**)&vthi, g_vthi); cudaGetSymbolAddress((void**)&vtlo, g_vtlo);

    const int M = MSZ;          // 8192
    const int KV = KVH_ * HD_;  // 1024

    // input/weight conversions
    {
        size_t nx = (size_t)M * D_;
        split_kernel<<<(unsigned)((nx + 255) / 256), 256>>>(x, xhi, xlo, nx);
        wsplit_t_kernel<<<dim3(D_ / 32, D_ / 32), dim3(32, 8)>>>(wq, wqh, wql, D_, D_);
        wsplit_t_kernel<<<dim3(KV / 32, D_ / 32), dim3(32, 8)>>>(wk, wkh, wkl, D_, KV);
        wsplit_t_kernel<<<dim3(KV / 32, D_ / 32), dim3(32, 8)>>>(wv, wvh, wvl, D_, KV);
        wsplit_t_kernel<<<dim3(D_ / 32, D_ / 32), dim3(32, 8)>>>(wo, woh, wol, D_, D_);
    }

    cudaFuncSetAttribute(gemm_mma, cudaFuncAttributeMaxDynamicSharedMemorySize, GEMM_SMEM);

    // QKV projections
    gemm_mma<<<dim3(D_ / 128, M / 128), 256, GEMM_SMEM>>>(xhi, xlo, wqh, wql, q, M, D_, D_);
    gemm_mma<<<dim3(KV / 128, M / 128), 256, GEMM_SMEM>>>(xhi, xlo, wkh, wkl, k, M, KV, D_);
    gemm_mma<<<dim3(KV / 128, M / 128), 256, GEMM_SMEM>>>(xhi, xlo, wvh, wvl, v, M, KV, D_);

    // RoPE + scale + split; V transpose + split
    {
        const float scale = 0.08838834764831845f;   // 1/sqrt(128), folded into q
        int np_q = B_ * S_ * H_ * (HD_ / 2);
        int np_k = B_ * S_ * KVH_ * (HD_ / 2);
        rope_split_kernel<<<(np_q + 255) / 256, 256>>>(q, pos_cos, pos_sin, qhi, qlo, H_, scale, np_q);
        rope_split_kernel<<<(np_k + 255) / 256, 256>>>(k, pos_cos, pos_sin, khi, klo, KVH_, 1.0f, np_k);
        vsplit_t_kernel<<<dim3(HD_ / 32, S_ / 32, B_ * KVH_), dim3(32, 8)>>>(v, vthi, vtlo);
    }

    // flash attention (mma.sync, split-bf16) -> athi/atlo
    cudaFuncSetAttribute(flash_mma, cudaFuncAttributeMaxDynamicSharedMemorySize, FLASH_SMEM);
    flash_mma<<<dim3(S_ / 128, H_, B_), 256, FLASH_SMEM>>>(qhi, qlo, khi, klo, vthi, vtlo, athi, atlo);

    // output projection -> d_out
    gemm_mma<<<dim3(D_ / 128, M / 128), 256, GEMM_SMEM>>>(athi, atlo, woh, wol, out, M, D_, D_);
}

// round 6
// speedup vs baseline: 2.6469x; 1.0127x over previous
#include <cuda_runtime.h>
#include <cuda_bf16.h>
#include <math.h>
#include <stdint.h>

#define B_   4
#define S_   2048
#define D_   2048
#define H_   16
#define KVH_ 8
#define HD_  128
#define MSZ  (B_ * S_)          // 8192

// ---------------- scratch (device globals; no allocation allowed) ----------------
__device__ float g_q[(size_t)MSZ * D_];                 // fp32 q after proj
__device__ float g_k[(size_t)MSZ * KVH_ * HD_];
__device__ float g_v[(size_t)MSZ * KVH_ * HD_];

__device__ __nv_bfloat16 g_xhi[(size_t)MSZ * D_];
__device__ __nv_bfloat16 g_xlo[(size_t)MSZ * D_];
__device__ __nv_bfloat16 g_wqh[(size_t)D_ * D_];
__device__ __nv_bfloat16 g_wql[(size_t)D_ * D_];
__device__ __nv_bfloat16 g_wkh[(size_t)D_ * KVH_ * HD_];
__device__ __nv_bfloat16 g_wkl[(size_t)D_ * KVH_ * HD_];
__device__ __nv_bfloat16 g_wvh[(size_t)D_ * KVH_ * HD_];
__device__ __nv_bfloat16 g_wvl[(size_t)D_ * KVH_ * HD_];
__device__ __nv_bfloat16 g_woh[(size_t)D_ * D_];
__device__ __nv_bfloat16 g_wol[(size_t)D_ * D_];
__device__ __nv_bfloat16 g_athi[(size_t)MSZ * D_];
__device__ __nv_bfloat16 g_atlo[(size_t)MSZ * D_];

// flash operands (bf16 splits)
__device__ __nv_bfloat16 g_qhi[(size_t)MSZ * D_];
__device__ __nv_bfloat16 g_qlo[(size_t)MSZ * D_];
__device__ __nv_bfloat16 g_khi[(size_t)MSZ * KVH_ * HD_];
__device__ __nv_bfloat16 g_klo[(size_t)MSZ * KVH_ * HD_];
__device__ __nv_bfloat16 g_vthi[(size_t)MSZ * KVH_ * HD_];   // [b][hk][d][s]
__device__ __nv_bfloat16 g_vtlo[(size_t)MSZ * KVH_ * HD_];

// ================= helpers (baseline PTX only) =================
__device__ __forceinline__ uint32_t smem_u32(const void* p) {
    uint32_t a;
    asm("{ .reg .u64 t; cvta.to.shared.u64 t, %1; cvt.u32.u64 %0, t; }" : "=r"(a) : "l"(p));
    return a;
}
__device__ __forceinline__ void cp_async16(uint32_t dst, const void* src) {
    asm volatile("cp.async.cg.shared.global [%0], [%1], 16;" :: "r"(dst), "l"(src) : "memory");
}
__device__ __forceinline__ void ldmatrix_x4(uint32_t* r, uint32_t addr) {
    asm volatile("ldmatrix.sync.aligned.m8n8.x4.shared.b16 {%0,%1,%2,%3}, [%4];"
                 : "=r"(r[0]), "=r"(r[1]), "=r"(r[2]), "=r"(r[3]) : "r"(addr));
}
__device__ __forceinline__ void mma_bf16(float* c, const uint32_t* a, uint32_t b0, uint32_t b1) {
    asm volatile("mma.sync.aligned.m16n8k16.row.col.f32.bf16.bf16.f32 "
                 "{%0,%1,%2,%3}, {%4,%5,%6,%7}, {%8,%9}, {%0,%1,%2,%3};"
                 : "+f"(c[0]), "+f"(c[1]), "+f"(c[2]), "+f"(c[3])
                 : "r"(a[0]), "r"(a[1]), "r"(a[2]), "r"(a[3]), "r"(b0), "r"(b1));
}
__device__ __forceinline__ float ex2f(float x) {
    float y;
    asm("ex2.approx.ftz.f32 %0, %1;" : "=f"(y) : "f"(x));
    return y;
}
__device__ __forceinline__ void split_pack(float f0, float f1, uint32_t& hi, uint32_t& lo) {
    __nv_bfloat16 h0 = __float2bfloat16(f0), h1 = __float2bfloat16(f1);
    __nv_bfloat16 l0 = __float2bfloat16(f0 - __bfloat162float(h0));
    __nv_bfloat16 l1 = __float2bfloat16(f1 - __bfloat162float(h1));
    __nv_bfloat162 Hv = __halves2bfloat162(h0, h1);
    __nv_bfloat162 Lv = __halves2bfloat162(l0, l1);
    hi = *(uint32_t*)&Hv; lo = *(uint32_t*)&Lv;
}
__device__ __forceinline__ void store_split2(__nv_bfloat16* hi, __nv_bfloat16* lo,
                                             size_t off, float f0, float f1) {
    __nv_bfloat16 h0 = __float2bfloat16(f0), h1 = __float2bfloat16(f1);
    *(__nv_bfloat162*)(hi + off) = __halves2bfloat162(h0, h1);
    *(__nv_bfloat162*)(lo + off) = __halves2bfloat162(
        __float2bfloat16(f0 - __bfloat162float(h0)),
        __float2bfloat16(f1 - __bfloat162float(h1)));
}

// ================= mma.sync GEMM (unchanged, proven) =================
#define TILE_H   5120
#define TILE_B   10240
#define STAGE_B  40960
#define GEMM_SMEM (2 * STAGE_B)

__global__ __launch_bounds__(256) void gemm_mma(const __nv_bfloat16* __restrict__ Ahi,
                                                const __nv_bfloat16* __restrict__ Alo,
                                                const __nv_bfloat16* __restrict__ Bhi,
                                                const __nv_bfloat16* __restrict__ Blo,
                                                float* __restrict__ C,
                                                int M, int N, int K) {
    extern __shared__ __align__(128) __nv_bfloat16 smh[];
    const int tid = threadIdx.x, lane = tid & 31, wid = tid >> 5;
    const int m0 = blockIdx.y * 128, n0 = blockIdx.x * 128;
    const int wm = (wid & 3) * 32, wn = (wid >> 2) * 64;
    const uint32_t sb = smem_u32(smh);

    const __nv_bfloat16* gsrc[4];
    gsrc[0] = Ahi + (size_t)m0 * K;
    gsrc[1] = Alo + (size_t)m0 * K;
    gsrc[2] = Bhi + (size_t)n0 * K;
    gsrc[3] = Blo + (size_t)n0 * K;

    auto load_chunk = [&](int c, int s) {
        const uint32_t st = sb + s * STAGE_B;
#pragma unroll
        for (int t = 0; t < 8; ++t) {
            int idx = t * 256 + tid;
            int tile = idx >> 9;
            int r = (idx >> 2) & 127;
            int seg = idx & 3;
            uint32_t dst = st + tile * TILE_B + r * 80 + seg * 16;
            cp_async16(dst, gsrc[tile] + (size_t)r * K + c * 32 + seg * 8);
        }
        asm volatile("cp.async.commit_group;" ::: "memory");
    };

    float acc[2][8][4];
#pragma unroll
    for (int mf = 0; mf < 2; ++mf)
#pragma unroll
        for (int nf = 0; nf < 8; ++nf)
#pragma unroll
            for (int e = 0; e < 4; ++e) acc[mf][nf][e] = 0.f;

    const int nch = K / 32;
    load_chunk(0, 0);
    load_chunk(1, 1);

    for (int i = 0; i < nch; ++i) {
        const int s = i & 1;
        if (i + 1 < nch) asm volatile("cp.async.wait_group 1;" ::: "memory");
        else             asm volatile("cp.async.wait_group 0;" ::: "memory");
        __syncthreads();

        const uint32_t st = sb + s * STAGE_B;
#pragma unroll
        for (int k16 = 0; k16 < 2; ++k16) {
            uint32_t ah[2][4], al[2][4];
#pragma unroll
            for (int mf = 0; mf < 2; ++mf) {
                int rowA = wm + mf * 16 + (lane & 15);
                int kA = k16 * 16 + ((lane >> 4) << 3);
                uint32_t off = (uint32_t)(rowA * 80 + kA * 2);
                ldmatrix_x4(ah[mf], st + off);
                ldmatrix_x4(al[mf], st + TILE_B + off);
            }
            uint32_t bh[4][4], bl[4][4];
#pragma unroll
            for (int nf2 = 0; nf2 < 4; ++nf2) {
                int rowB = wn + nf2 * 16 + (lane & 7) + ((lane >> 4) << 3);
                int kB = k16 * 16 + (((lane >> 3) & 1) << 3);
                uint32_t off = (uint32_t)(rowB * 80 + kB * 2);
                ldmatrix_x4(bh[nf2], st + 2 * TILE_B + off);
                ldmatrix_x4(bl[nf2], st + 3 * TILE_B + off);
            }
#pragma unroll
            for (int mf = 0; mf < 2; ++mf)
#pragma unroll
                for (int nf = 0; nf < 8; ++nf) {
                    uint32_t b0h = bh[nf >> 1][(nf & 1) * 2], b1h = bh[nf >> 1][(nf & 1) * 2 + 1];
                    uint32_t b0l = bl[nf >> 1][(nf & 1) * 2], b1l = bl[nf >> 1][(nf & 1) * 2 + 1];
                    mma_bf16(acc[mf][nf], ah[mf], b0h, b1h);
                    mma_bf16(acc[mf][nf], ah[mf], b0l, b1l);
                    mma_bf16(acc[mf][nf], al[mf], b0h, b1h);
                }
        }
        __syncthreads();
        if (i + 2 < nch) load_chunk(i + 2, s);
    }

#pragma unroll
    for (int mf = 0; mf < 2; ++mf) {
        int row = m0 + wm + mf * 16 + (lane >> 2);
#pragma unroll
        for (int nf = 0; nf < 8; ++nf) {
            int col = n0 + wn + nf * 8 + (lane & 3) * 2;
            *(float2*)&C[(size_t)row * N + col] = make_float2(acc[mf][nf][0], acc[mf][nf][1]);
            *(float2*)&C[(size_t)(row + 8) * N + col] = make_float2(acc[mf][nf][2], acc[mf][nf][3]);
        }
    }
}

// ================= fp32 -> bf16 hi/lo split (elementwise) =================
__global__ __launch_bounds__(256) void split_kernel(const float* __restrict__ v,
                                                    __nv_bfloat16* __restrict__ hi,
                                                    __nv_bfloat16* __restrict__ lo,
                                                    size_t n) {
    size_t i = (size_t)blockIdx.x * blockDim.x + threadIdx.x;
    if (i >= n) return;
    float f = v[i];
    __nv_bfloat16 h = __float2bfloat16(f);
    hi[i] = h;
    lo[i] = __float2bfloat16(f - __bfloat162float(h));
}

// ================= weight transpose + split =================
__global__ __launch_bounds__(256) void wsplit_t_kernel(const float* __restrict__ W,
                                                       __nv_bfloat16* __restrict__ hi,
                                                       __nv_bfloat16* __restrict__ lo,
                                                       int Kd, int Nd) {
    __shared__ float t[32][33];
    int k0 = blockIdx.y * 32, n0 = blockIdx.x * 32;
    int x = threadIdx.x, y = threadIdx.y;
#pragma unroll
    for (int i = 0; i < 32; i += 8)
        t[y + i][x] = W[(size_t)(k0 + y + i) * Nd + n0 + x];
    __syncthreads();
#pragma unroll
    for (int i = 0; i < 32; i += 8) {
        float f = t[x][y + i];
        __nv_bfloat16 h = __float2bfloat16(f);
        size_t o = (size_t)(n0 + y + i) * Kd + k0 + x;
        hi[o] = h;
        lo[o] = __float2bfloat16(f - __bfloat162float(h));
    }
}

// ================= RoPE + scale + split (fp32 in, bf16 hi/lo out) =================
__global__ __launch_bounds__(256) void rope_split_kernel(const float* __restrict__ t,
                                                         const float* __restrict__ co,
                                                         const float* __restrict__ si,
                                                         __nv_bfloat16* __restrict__ hi,
                                                         __nv_bfloat16* __restrict__ lo,
                                                         int nh, float scale, int npairs) {
    int idx = blockIdx.x * blockDim.x + threadIdx.x;
    if (idx >= npairs) return;
    int i = idx & 63;
    int s = ((idx >> 6) / nh) % S_;
    float c  = co[s * 64 + i];
    float sn = si[s * 64 + i];
    float2 v = *(const float2*)&t[(size_t)idx * 2];
    float o0 = (v.x * c - v.y * sn) * scale;
    float o1 = (v.x * sn + v.y * c) * scale;
    store_split2(hi, lo, (size_t)idx * 2, o0, o1);
}

// ================= V transpose + split: v[b][s][hk][d] -> vt[b][hk][d][s] =================
__global__ __launch_bounds__(256) void vsplit_t_kernel(const float* __restrict__ v,
                                                       __nv_bfloat16* __restrict__ hi,
                                                       __nv_bfloat16* __restrict__ lo) {
    __shared__ float t[32][33];
    int bz = blockIdx.z;
    int b = bz >> 3, hk = bz & 7;
    int s0 = blockIdx.y * 32, d0 = blockIdx.x * 32;
    int x = threadIdx.x, y = threadIdx.y;
#pragma unroll
    for (int i = 0; i < 32; i += 8)
        t[y + i][x] = v[(((size_t)b * S_ + s0 + y + i) * KVH_ + hk) * HD_ + d0 + x];
    __syncthreads();
#pragma unroll
    for (int i = 0; i < 32; i += 8) {
        float f = t[x][y + i];
        __nv_bfloat16 h = __float2bfloat16(f);
        size_t o = (((size_t)b * KVH_ + hk) * HD_ + d0 + y + i) * S_ + s0 + x;
        hi[o] = h;
        lo[o] = __float2bfloat16(f - __bfloat162float(h));
    }
}

// ================= flash attention v2: Q in registers, 3-stage KV, 1 sync/tile =================
// CTA: 128 q-rows x one (b,h). 8 warps, 16 rows each. KV tiles of 64.
// Scores arrive pre-scaled by log2(e) (folded into q), softmax uses ex2.
#define FQ_ST 272               // K rows / Q rows: 136 halves stride
#define FV_ST 144               // V^T rows: 72 halves stride
#define SK_SPLIT 17408          // 64*272
#define SV_SPLIT 18432          // 128*144
#define FSTAGE (2 * SK_SPLIT + 2 * SV_SPLIT)    // 71680
#define FLASH_SMEM (3 * FSTAGE)                 // 215040
#define QLO_OFF 34816           // qlo offset inside Q staging (128*272)

__global__ __launch_bounds__(256) void flash_mma(
    const __nv_bfloat16* __restrict__ qhi, const __nv_bfloat16* __restrict__ qlo,
    const __nv_bfloat16* __restrict__ khi, const __nv_bfloat16* __restrict__ klo,
    const __nv_bfloat16* __restrict__ vthi, const __nv_bfloat16* __restrict__ vtlo,
    __nv_bfloat16* __restrict__ athi, __nv_bfloat16* __restrict__ atlo) {
    extern __shared__ __align__(128) char smc[];
    const uint32_t sb = smem_u32(smc);
    const int tid = threadIdx.x, lane = tid & 31, w = tid >> 5;
    const int qt = (int)gridDim.x - 1 - (int)blockIdx.x;   // heavy CTAs first
    const int h = blockIdx.y, b = blockIdx.z, hk = h >> 1;
    const int q0 = qt * 128;
    const int ntiles = 2 * qt + 2;

    auto load_tile = [&](int j, int s) {
        const uint32_t stb = sb + s * FSTAGE;
#pragma unroll
        for (int t = 0; t < 4; ++t) {
            int idx = t * 256 + tid;
            int r = idx >> 4, seg = idx & 15;
            size_t go = (((size_t)b * S_ + j * 64 + r) * KVH_ + hk) * HD_ + seg * 8;
            uint32_t d = stb + (uint32_t)(r * FQ_ST + seg * 16);
            cp_async16(d, khi + go);
            cp_async16(d + SK_SPLIT, klo + go);
        }
#pragma unroll
        for (int t = 0; t < 4; ++t) {
            int idx = t * 256 + tid;
            int dd = idx >> 3, seg = idx & 7;
            size_t go = (((size_t)b * KVH_ + hk) * HD_ + dd) * S_ + j * 64 + seg * 8;
            uint32_t d = stb + 2 * SK_SPLIT + (uint32_t)(dd * FV_ST + seg * 16);
            cp_async16(d, vthi + go);
            cp_async16(d + SV_SPLIT, vtlo + go);
        }
        asm volatile("cp.async.commit_group;" ::: "memory");
    };

    // -- prologue: Q staged into buffer 2, KV tiles 0/1 into buffers 0/1 (3 groups) --
    {
        const uint32_t st2 = sb + 2 * FSTAGE;
#pragma unroll
        for (int t = 0; t < 8; ++t) {
            int idx = t * 256 + tid;
            int r = idx >> 4, seg = idx & 15;
            size_t go = (((size_t)b * S_ + q0 + r) * H_ + h) * HD_ + seg * 8;
            uint32_t d = st2 + (uint32_t)(r * FQ_ST + seg * 16);
            cp_async16(d, qhi + go);
            cp_async16(d + QLO_OFF, qlo + go);
        }
        asm volatile("cp.async.commit_group;" ::: "memory");
    }
    load_tile(0, 0);
    load_tile(1, 1);

    // wait for Q (2 later groups may remain in flight), pull Q fragments to registers
    asm volatile("cp.async.wait_group 2;" ::: "memory");
    __syncthreads();
    uint32_t qh[8][4], ql[8][4];
    {
        const uint32_t st2 = sb + 2 * FSTAGE;
#pragma unroll
        for (int k16 = 0; k16 < 8; ++k16) {
            uint32_t offA = (uint32_t)((w * 16 + (lane & 15)) * FQ_ST +
                                       (k16 * 16 + ((lane >> 4) << 3)) * 2);
            ldmatrix_x4(qh[k16], st2 + offA);
            ldmatrix_x4(ql[k16], st2 + QLO_OFF + offA);
        }
    }
    __syncthreads();   // all warps done reading buffer 2 before tile-2 load reuses it

    float o[16][4];
#pragma unroll
    for (int nf = 0; nf < 16; ++nf)
#pragma unroll
        for (int e = 0; e < 4; ++e) o[nf][e] = 0.f;
    float mA = -1e30f, mB = -1e30f, lA = 0.f, lB = 0.f;

    const int rowTopA = q0 + w * 16 + 15;   // max row this warp owns

    for (int i = 0; i < ntiles; ++i) {
        if (i + 1 < ntiles) asm volatile("cp.async.wait_group 1;" ::: "memory");
        else                asm volatile("cp.async.wait_group 0;" ::: "memory");
        __syncthreads();
        if (i + 2 < ntiles) load_tile(i + 2, (i + 2) % 3);

        const bool active = rowTopA >= i * 64;   // warp has at least one unmasked element
        if (active) {
            const uint32_t st = sb + (i % 3) * FSTAGE;

            // ---- S = Q K^T (3-pass split; Q from registers) ----
            float c[8][4];
#pragma unroll
            for (int nf = 0; nf < 8; ++nf)
#pragma unroll
                for (int e = 0; e < 4; ++e) c[nf][e] = 0.f;

#pragma unroll
            for (int k16 = 0; k16 < 8; ++k16) {
                uint32_t bh[4][4], bl[4][4];
#pragma unroll
                for (int nf2 = 0; nf2 < 4; ++nf2) {
                    uint32_t offB = (uint32_t)((nf2 * 16 + (lane & 7) + ((lane >> 4) << 3)) * FQ_ST +
                                               (k16 * 16 + (((lane >> 3) & 1) << 3)) * 2);
                    ldmatrix_x4(bh[nf2], st + offB);
                    ldmatrix_x4(bl[nf2], st + SK_SPLIT + offB);
                }
#pragma unroll
                for (int nf = 0; nf < 8; ++nf) {
                    uint32_t b0h = bh[nf >> 1][(nf & 1) * 2], b1h = bh[nf >> 1][(nf & 1) * 2 + 1];
                    uint32_t b0l = bl[nf >> 1][(nf & 1) * 2], b1l = bl[nf >> 1][(nf & 1) * 2 + 1];
                    mma_bf16(c[nf], qh[k16], b0h, b1h);
                    mma_bf16(c[nf], qh[k16], b0l, b1l);
                    mma_bf16(c[nf], ql[k16], b0h, b1h);
                }
            }

            // ---- causal mask (diagonal tiles only) ----
            if (i >= 2 * qt) {
                int rowA = q0 + w * 16 + (lane >> 2);
                int colb = i * 64 + (lane & 3) * 2;
#pragma unroll
                for (int nf = 0; nf < 8; ++nf) {
                    int c0 = colb + nf * 8, c1 = c0 + 1;
                    if (c0 > rowA) c[nf][0] = -1e30f;
                    if (c1 > rowA) c[nf][1] = -1e30f;
                    if (c0 > rowA + 8) c[nf][2] = -1e30f;
                    if (c1 > rowA + 8) c[nf][3] = -1e30f;
                }
            }

            // ---- online softmax in log2 domain (scores pre-scaled by log2e) ----
            float mtA = -1e30f, mtB = -1e30f;
#pragma unroll
            for (int nf = 0; nf < 8; ++nf) {
                mtA = fmaxf(mtA, fmaxf(c[nf][0], c[nf][1]));
                mtB = fmaxf(mtB, fmaxf(c[nf][2], c[nf][3]));
            }
            mtA = fmaxf(mtA, __shfl_xor_sync(0xffffffffu, mtA, 1));
            mtA = fmaxf(mtA, __shfl_xor_sync(0xffffffffu, mtA, 2));
            mtB = fmaxf(mtB, __shfl_xor_sync(0xffffffffu, mtB, 1));
            mtB = fmaxf(mtB, __shfl_xor_sync(0xffffffffu, mtB, 2));
            float mnA = fmaxf(mA, mtA), mnB = fmaxf(mB, mtB);
            float aA = ex2f(mA - mnA), aB = ex2f(mB - mnB);
            mA = mnA; mB = mnB;
            float rsA = 0.f, rsB = 0.f;
#pragma unroll
            for (int nf = 0; nf < 8; ++nf) {
                c[nf][0] = ex2f(c[nf][0] - mnA);
                c[nf][1] = ex2f(c[nf][1] - mnA);
                c[nf][2] = ex2f(c[nf][2] - mnB);
                c[nf][3] = ex2f(c[nf][3] - mnB);
                rsA += c[nf][0] + c[nf][1];
                rsB += c[nf][2] + c[nf][3];
            }
            rsA += __shfl_xor_sync(0xffffffffu, rsA, 1);
            rsA += __shfl_xor_sync(0xffffffffu, rsA, 2);
            rsB += __shfl_xor_sync(0xffffffffu, rsB, 1);
            rsB += __shfl_xor_sync(0xffffffffu, rsB, 2);
            lA = lA * aA + rsA;
            lB = lB * aB + rsB;
#pragma unroll
            for (int nf = 0; nf < 16; ++nf) {
                o[nf][0] *= aA; o[nf][1] *= aA;
                o[nf][2] *= aB; o[nf][3] *= aB;
            }

            // ---- O += P V (3-pass split; P C-frag -> A-frag in registers) ----
            const uint32_t stv = st + 2 * SK_SPLIT;
#pragma unroll
            for (int kc = 0; kc < 4; ++kc) {
                uint32_t ph[4], pl[4];
                split_pack(c[2 * kc][0],     c[2 * kc][1],     ph[0], pl[0]);
                split_pack(c[2 * kc][2],     c[2 * kc][3],     ph[1], pl[1]);
                split_pack(c[2 * kc + 1][0], c[2 * kc + 1][1], ph[2], pl[2]);
                split_pack(c[2 * kc + 1][2], c[2 * kc + 1][3], ph[3], pl[3]);
#pragma unroll
                for (int nf2 = 0; nf2 < 8; ++nf2) {
                    uint32_t offV = (uint32_t)((nf2 * 16 + (lane & 7) + ((lane >> 4) << 3)) * FV_ST +
                                               (kc * 16 + (((lane >> 3) & 1) << 3)) * 2);
                    uint32_t vh[4], vl[4];
                    ldmatrix_x4(vh, stv + offV);
                    ldmatrix_x4(vl, stv + SV_SPLIT + offV);
#pragma unroll
                    for (int t = 0; t < 2; ++t) {
                        int nf = nf2 * 2 + t;
                        mma_bf16(o[nf], ph, vh[t * 2], vh[t * 2 + 1]);
                        mma_bf16(o[nf], ph, vl[t * 2], vl[t * 2 + 1]);
                        mma_bf16(o[nf], pl, vh[t * 2], vh[t * 2 + 1]);
                    }
                }
            }
        }
    }

    // ---- epilogue: O/l -> athi/atlo ----
    float iA = 1.f / lA, iB = 1.f / lB;
    int rowA = q0 + w * 16 + (lane >> 2);
#pragma unroll
    for (int nf = 0; nf < 16; ++nf) {
        int dcol = nf * 8 + (lane & 3) * 2;
        size_t oA = (((size_t)b * S_ + rowA) * H_ + h) * HD_ + dcol;
        size_t oB = (((size_t)b * S_ + rowA + 8) * H_ + h) * HD_ + dcol;
        store_split2(athi, atlo, oA, o[nf][0] * iA, o[nf][1] * iA);
        store_split2(athi, atlo, oB, o[nf][2] * iB, o[nf][3] * iB);
    }
}

// ---------------- host ----------------
extern "C" void kernel_launch(void* const* d_in, const int* in_sizes, int n_in,
                              void* d_out, int out_size) {
    const float* x       = (const float*)d_in[0];
    const float* wq      = (const float*)d_in[1];
    const float* wk      = (const float*)d_in[2];
    const float* wv      = (const float*)d_in[3];
    const float* wo      = (const float*)d_in[4];
    const float* pos_cos = (const float*)d_in[5];
    const float* pos_sin = (const float*)d_in[6];
    float* out = (float*)d_out;

    float *q, *k, *v;
    cudaGetSymbolAddress((void**)&q, g_q);
    cudaGetSymbolAddress((void**)&k, g_k);
    cudaGetSymbolAddress((void**)&v, g_v);
    __nv_bfloat16 *xhi, *xlo, *wqh, *wql, *wkh, *wkl, *wvh, *wvl, *woh, *wol, *athi, *atlo;
    __nv_bfloat16 *qhi, *qlo, *khi, *klo, *vthi, *vtlo;
    cudaGetSymbolAddress((void**)&xhi, g_xhi);  cudaGetSymbolAddress((void**)&xlo, g_xlo);
    cudaGetSymbolAddress((void**)&wqh, g_wqh);  cudaGetSymbolAddress((void**)&wql, g_wql);
    cudaGetSymbolAddress((void**)&wkh, g_wkh);  cudaGetSymbolAddress((void**)&wkl, g_wkl);
    cudaGetSymbolAddress((void**)&wvh, g_wvh);  cudaGetSymbolAddress((void**)&wvl, g_wvl);
    cudaGetSymbolAddress((void**)&woh, g_woh);  cudaGetSymbolAddress((void**)&wol, g_wol);
    cudaGetSymbolAddress((void**)&athi, g_athi); cudaGetSymbolAddress((void**)&atlo, g_atlo);
    cudaGetSymbolAddress((void**)&qhi, g_qhi);  cudaGetSymbolAddress((void**)&qlo, g_qlo);
    cudaGetSymbolAddress((void**)&khi, g_khi);  cudaGetSymbolAddress((void**)&klo, g_klo);
    cudaGetSymbolAddress((void**)&vthi, g_vthi); cudaGetSymbolAddress((void**)&vtlo, g_vtlo);

    const int M = MSZ;          // 8192
    const int KV = KVH_ * HD_;  // 1024

    // input/weight conversions
    {
        size_t nx = (size_t)M * D_;
        split_kernel<<<(unsigned)((nx + 255) / 256), 256>>>(x, xhi, xlo, nx);
        wsplit_t_kernel<<<dim3(D_ / 32, D_ / 32), dim3(32, 8)>>>(wq, wqh, wql, D_, D_);
        wsplit_t_kernel<<<dim3(KV / 32, D_ / 32), dim3(32, 8)>>>(wk, wkh, wkl, D_, KV);
        wsplit_t_kernel<<<dim3(KV / 32, D_ / 32), dim3(32, 8)>>>(wv, wvh, wvl, D_, KV);
        wsplit_t_kernel<<<dim3(D_ / 32, D_ / 32), dim3(32, 8)>>>(wo, woh, wol, D_, D_);
    }

    cudaFuncSetAttribute(gemm_mma, cudaFuncAttributeMaxDynamicSharedMemorySize, GEMM_SMEM);

    // QKV projections
    gemm_mma<<<dim3(D_ / 128, M / 128), 256, GEMM_SMEM>>>(xhi, xlo, wqh, wql, q, M, D_, D_);
    gemm_mma<<<dim3(KV / 128, M / 128), 256, GEMM_SMEM>>>(xhi, xlo, wkh, wkl, k, M, KV, D_);
    gemm_mma<<<dim3(KV / 128, M / 128), 256, GEMM_SMEM>>>(xhi, xlo, wvh, wvl, v, M, KV, D_);

    // RoPE + scale + split; V transpose + split
    {
        // q gets 1/sqrt(HD) * log2(e) so softmax can run in exp2 domain
        const float scale = 0.08838834764831845f * 1.4426950408889634f;
        int np_q = B_ * S_ * H_ * (HD_ / 2);
        int np_k = B_ * S_ * KVH_ * (HD_ / 2);
        rope_split_kernel<<<(np_q + 255) / 256, 256>>>(q, pos_cos, pos_sin, qhi, qlo, H_, scale, np_q);
        rope_split_kernel<<<(np_k + 255) / 256, 256>>>(k, pos_cos, pos_sin, khi, klo, KVH_, 1.0f, np_k);
        vsplit_t_kernel<<<dim3(HD_ / 32, S_ / 32, B_ * KVH_), dim3(32, 8)>>>(v, vthi, vtlo);
    }

    // flash attention v2 -> athi/atlo
    cudaFuncSetAttribute(flash_mma, cudaFuncAttributeMaxDynamicSharedMemorySize, FLASH_SMEM);
    flash_mma<<<dim3(S_ / 128, H_, B_), 256, FLASH_SMEM>>>(qhi, qlo, khi, klo, vthi, vtlo, athi, atlo);

    // output projection -> d_out
    gemm_mma<<<dim3(D_ / 128, M / 128), 256, GEMM_SMEM>>>(athi, atlo, woh, wol, out, M, D_, D_);
}

// round 8
// speedup vs baseline: 3.4366x; 1.2984x over previous
#include <cuda_runtime.h>
#include <cuda_fp16.h>
#include <math.h>
#include <stdint.h>

#define B_   4
#define S_   2048
#define D_   2048
#define H_   16
#define KVH_ 8
#define HD_  128
#define MSZ  (B_ * S_)          // 8192

// ---------------- scratch (device globals; no allocation allowed) ----------------
__device__ float  g_v[(size_t)MSZ * KVH_ * HD_];        // fp32 v after proj (for transpose)

__device__ __half g_xhi[(size_t)MSZ * D_];
__device__ __half g_xlo[(size_t)MSZ * D_];
__device__ __half g_wqh[(size_t)D_ * D_];
__device__ __half g_wkh[(size_t)D_ * KVH_ * HD_];
__device__ __half g_wvh[(size_t)D_ * KVH_ * HD_];
__device__ __half g_woh[(size_t)D_ * D_];
__device__ __half g_athi[(size_t)MSZ * D_];
__device__ __half g_atlo[(size_t)MSZ * D_];

__device__ __half g_qhi[(size_t)MSZ * D_];
__device__ __half g_qlo[(size_t)MSZ * D_];
__device__ __half g_khi[(size_t)MSZ * KVH_ * HD_];
__device__ __half g_klo[(size_t)MSZ * KVH_ * HD_];
__device__ __half g_vthi[(size_t)MSZ * KVH_ * HD_];     // [b][hk][d][s]
__device__ __half g_vtlo[(size_t)MSZ * KVH_ * HD_];

// ================= helpers (baseline PTX only) =================
__device__ __forceinline__ uint32_t smem_u32(const void* p) {
    uint32_t a;
    asm("{ .reg .u64 t; cvta.to.shared.u64 t, %1; cvt.u32.u64 %0, t; }" : "=r"(a) : "l"(p));
    return a;
}
__device__ __forceinline__ void cp_async16(uint32_t dst, const void* src) {
    asm volatile("cp.async.cg.shared.global [%0], [%1], 16;" :: "r"(dst), "l"(src) : "memory");
}
__device__ __forceinline__ void ldmatrix_x4(uint32_t* r, uint32_t addr) {
    asm volatile("ldmatrix.sync.aligned.m8n8.x4.shared.b16 {%0,%1,%2,%3}, [%4];"
                 : "=r"(r[0]), "=r"(r[1]), "=r"(r[2]), "=r"(r[3]) : "r"(addr));
}
__device__ __forceinline__ void mma_f16(float* c, const uint32_t* a, uint32_t b0, uint32_t b1) {
    asm volatile("mma.sync.aligned.m16n8k16.row.col.f32.f16.f16.f32 "
                 "{%0,%1,%2,%3}, {%4,%5,%6,%7}, {%8,%9}, {%0,%1,%2,%3};"
                 : "+f"(c[0]), "+f"(c[1]), "+f"(c[2]), "+f"(c[3])
                 : "r"(a[0]), "r"(a[1]), "r"(a[2]), "r"(a[3]), "r"(b0), "r"(b1));
}
__device__ __forceinline__ float ex2f(float x) {
    float y;
    asm("ex2.approx.ftz.f32 %0, %1;" : "=f"(y) : "f"(x));
    return y;
}
__device__ __forceinline__ void split_pack_h(float f0, float f1, uint32_t& hi, uint32_t& lo) {
    __half h0 = __float2half_rn(f0), h1 = __float2half_rn(f1);
    __half l0 = __float2half_rn(f0 - __half2float(h0));
    __half l1 = __float2half_rn(f1 - __half2float(h1));
    __half2 Hv = __halves2half2(h0, h1);
    __half2 Lv = __halves2half2(l0, l1);
    hi = *(uint32_t*)&Hv; lo = *(uint32_t*)&Lv;
}
__device__ __forceinline__ void store_split2h(__half* hi, __half* lo,
                                              size_t off, float f0, float f1) {
    __half h0 = __float2half_rn(f0), h1 = __float2half_rn(f1);
    *(__half2*)(hi + off) = __halves2half2(h0, h1);
    *(__half2*)(lo + off) = __halves2half2(
        __float2half_rn(f0 - __half2float(h0)),
        __float2half_rn(f1 - __half2float(h1)));
}

// ================= 2-pass fp16 GEMM: C = (Ahi+Alo)·Bhi^T =================
// A: [M,K] fp16 hi/lo; B: [N,K] fp16 hi (weights pre-transposed, rounded).
// CTA 128x128, K-chunk 32, 256 threads (8 warps, each 32x64), double-buffered cp.async.
// mode 0: fp32 C store. mode 1: RoPE(+scale) applied to fragment pairs, split fp16 store.
#define TILE_B   10240          // 128 rows x 80 bytes
#define STAGE2_B (3 * TILE_B)   // Ah, Al, Bh
#define GEMM_SMEM (2 * STAGE2_B)

__global__ __launch_bounds__(256) void gemm2(const __half* __restrict__ Ahi,
                                             const __half* __restrict__ Alo,
                                             const __half* __restrict__ Bh,
                                             float* __restrict__ C,
                                             __half* __restrict__ Ohi,
                                             __half* __restrict__ Olo,
                                             const float* __restrict__ co,
                                             const float* __restrict__ si,
                                             float scale,
                                             int M, int N, int K, int mode) {
    extern __shared__ __align__(128) char smh[];
    const int tid = threadIdx.x, lane = tid & 31, wid = tid >> 5;
    const int m0 = blockIdx.y * 128, n0 = blockIdx.x * 128;
    const int wm = (wid & 3) * 32, wn = (wid >> 2) * 64;
    const uint32_t sb = smem_u32(smh);

    const __half* gsrc[3];
    gsrc[0] = Ahi + (size_t)m0 * K;
    gsrc[1] = Alo + (size_t)m0 * K;
    gsrc[2] = Bh + (size_t)n0 * K;

    auto load_chunk = [&](int c, int s) {
        const uint32_t st = sb + s * STAGE2_B;
#pragma unroll
        for (int t = 0; t < 6; ++t) {
            int idx = t * 256 + tid;          // 0..1535
            int tile = idx >> 9;              // 0..2
            int r = (idx >> 2) & 127;
            int seg = idx & 3;
            uint32_t dst = st + tile * TILE_B + r * 80 + seg * 16;
            cp_async16(dst, gsrc[tile] + (size_t)r * K + c * 32 + seg * 8);
        }
        asm volatile("cp.async.commit_group;" ::: "memory");
    };

    float acc[2][8][4];
#pragma unroll
    for (int mf = 0; mf < 2; ++mf)
#pragma unroll
        for (int nf = 0; nf < 8; ++nf)
#pragma unroll
            for (int e = 0; e < 4; ++e) acc[mf][nf][e] = 0.f;

    const int nch = K / 32;
    load_chunk(0, 0);
    load_chunk(1, 1);

    for (int i = 0; i < nch; ++i) {
        const int s = i & 1;
        if (i + 1 < nch) asm volatile("cp.async.wait_group 1;" ::: "memory");
        else             asm volatile("cp.async.wait_group 0;" ::: "memory");
        __syncthreads();

        const uint32_t st = sb + s * STAGE2_B;
#pragma unroll
        for (int k16 = 0; k16 < 2; ++k16) {
            uint32_t ah[2][4], al[2][4];
#pragma unroll
            for (int mf = 0; mf < 2; ++mf) {
                int rowA = wm + mf * 16 + (lane & 15);
                int kA = k16 * 16 + ((lane >> 4) << 3);
                uint32_t off = (uint32_t)(rowA * 80 + kA * 2);
                ldmatrix_x4(ah[mf], st + off);
                ldmatrix_x4(al[mf], st + TILE_B + off);
            }
            uint32_t bh[4][4];
#pragma unroll
            for (int nf2 = 0; nf2 < 4; ++nf2) {
                int rowB = wn + nf2 * 16 + (lane & 7) + ((lane >> 4) << 3);
                int kB = k16 * 16 + (((lane >> 3) & 1) << 3);
                uint32_t off = (uint32_t)(rowB * 80 + kB * 2);
                ldmatrix_x4(bh[nf2], st + 2 * TILE_B + off);
            }
#pragma unroll
            for (int mf = 0; mf < 2; ++mf)
#pragma unroll
                for (int nf = 0; nf < 8; ++nf) {
                    uint32_t b0 = bh[nf >> 1][(nf & 1) * 2], b1 = bh[nf >> 1][(nf & 1) * 2 + 1];
                    mma_f16(acc[mf][nf], ah[mf], b0, b1);
                    mma_f16(acc[mf][nf], al[mf], b0, b1);
                }
        }
        __syncthreads();
        if (i + 2 < nch) load_chunk(i + 2, s);
    }

    if (mode == 0) {
#pragma unroll
        for (int mf = 0; mf < 2; ++mf) {
            int row = m0 + wm + mf * 16 + (lane >> 2);
#pragma unroll
            for (int nf = 0; nf < 8; ++nf) {
                int col = n0 + wn + nf * 8 + (lane & 3) * 2;
                *(float2*)&C[(size_t)row * N + col] = make_float2(acc[mf][nf][0], acc[mf][nf][1]);
                *(float2*)&C[(size_t)(row + 8) * N + col] = make_float2(acc[mf][nf][2], acc[mf][nf][3]);
            }
        }
    } else {
        // RoPE + scale + fp16 split store. Fragment cols (col, col+1) form a RoPE pair.
#pragma unroll
        for (int mf = 0; mf < 2; ++mf) {
            int row = m0 + wm + mf * 16 + (lane >> 2);
            int s0 = row & (S_ - 1);
            int s1 = (row + 8) & (S_ - 1);
#pragma unroll
            for (int nf = 0; nf < 8; ++nf) {
                int col = n0 + wn + nf * 8 + (lane & 3) * 2;
                int fi = (col & (HD_ - 1)) >> 1;
                float c0 = co[s0 * 64 + fi], sn0 = si[s0 * 64 + fi];
                float c1 = co[s1 * 64 + fi], sn1 = si[s1 * 64 + fi];
                float a0 = acc[mf][nf][0], a1 = acc[mf][nf][1];
                float b0 = acc[mf][nf][2], b1 = acc[mf][nf][3];
                store_split2h(Ohi, Olo, (size_t)row * N + col,
                              (a0 * c0 - a1 * sn0) * scale, (a0 * sn0 + a1 * c0) * scale);
                store_split2h(Ohi, Olo, (size_t)(row + 8) * N + col,
                              (b0 * c1 - b1 * sn1) * scale, (b0 * sn1 + b1 * c1) * scale);
            }
        }
    }
}

// ================= fp32 -> fp16 hi/lo split (elementwise) =================
__global__ __launch_bounds__(256) void split_kernel(const float* __restrict__ v,
                                                    __half* __restrict__ hi,
                                                    __half* __restrict__ lo,
                                                    size_t n) {
    size_t i = (size_t)blockIdx.x * blockDim.x + threadIdx.x;
    if (i >= n) return;
    float f = v[i];
    __half h = __float2half_rn(f);
    hi[i] = h;
    lo[i] = __float2half_rn(f - __half2float(h));
}

// ================= weight transpose + fp16 round (hi only) =================
__global__ __launch_bounds__(256) void whalf_t_kernel(const float* __restrict__ W,
                                                      __half* __restrict__ hi,
                                                      int Kd, int Nd) {
    __shared__ float t[32][33];
    int k0 = blockIdx.y * 32, n0 = blockIdx.x * 32;
    int x = threadIdx.x, y = threadIdx.y;
#pragma unroll
    for (int i = 0; i < 32; i += 8)
        t[y + i][x] = W[(size_t)(k0 + y + i) * Nd + n0 + x];
    __syncthreads();
#pragma unroll
    for (int i = 0; i < 32; i += 8)
        hi[(size_t)(n0 + y + i) * Kd + k0 + x] = __float2half_rn(t[x][y + i]);
}

// ================= V transpose + split: v[b][s][hk][d] -> vt[b][hk][d][s] =================
__global__ __launch_bounds__(256) void vsplit_t_kernel(const float* __restrict__ v,
                                                       __half* __restrict__ hi,
                                                       __half* __restrict__ lo) {
    __shared__ float t[32][33];
    int bz = blockIdx.z;
    int b = bz >> 3, hk = bz & 7;
    int s0 = blockIdx.y * 32, d0 = blockIdx.x * 32;
    int x = threadIdx.x, y = threadIdx.y;
#pragma unroll
    for (int i = 0; i < 32; i += 8)
        t[y + i][x] = v[(((size_t)b * S_ + s0 + y + i) * KVH_ + hk) * HD_ + d0 + x];
    __syncthreads();
#pragma unroll
    for (int i = 0; i < 32; i += 8) {
        float f = t[x][y + i];
        __half h = __float2half_rn(f);
        size_t o = (((size_t)b * KVH_ + hk) * HD_ + d0 + y + i) * S_ + s0 + x;
        hi[o] = h;
        lo[o] = __float2half_rn(f - __half2float(h));
    }
}

// ================= flash attention (fp16, 3-pass split), causal, GQA =================
// CTA: 128 q-rows x one (b,h). 8 warps, 16 rows each. KV tiles of 64, 3-stage pipeline.
// Scores pre-scaled by log2(e); softmax in exp2 domain.
#define FQ_ST 272
#define FV_ST 144
#define SK_SPLIT 17408
#define SV_SPLIT 18432
#define FSTAGE (2 * SK_SPLIT + 2 * SV_SPLIT)    // 71680
#define FLASH_SMEM (3 * FSTAGE)                 // 215040
#define QLO_OFF 34816

__global__ __launch_bounds__(256) void flash_mma(
    const __half* __restrict__ qhi, const __half* __restrict__ qlo,
    const __half* __restrict__ khi, const __half* __restrict__ klo,
    const __half* __restrict__ vthi, const __half* __restrict__ vtlo,
    __half* __restrict__ athi, __half* __restrict__ atlo) {
    extern __shared__ __align__(128) char smc[];
    const uint32_t sb = smem_u32(smc);
    const int tid = threadIdx.x, lane = tid & 31, w = tid >> 5;
    const int qt = (int)gridDim.x - 1 - (int)blockIdx.x;
    const int h = blockIdx.y, b = blockIdx.z, hk = h >> 1;
    const int q0 = qt * 128;
    const int ntiles = 2 * qt + 2;

    auto load_tile = [&](int j, int s) {
        const uint32_t stb = sb + s * FSTAGE;
#pragma unroll
        for (int t = 0; t < 4; ++t) {
            int idx = t * 256 + tid;
            int r = idx >> 4, seg = idx & 15;
            size_t go = (((size_t)b * S_ + j * 64 + r) * KVH_ + hk) * HD_ + seg * 8;
            uint32_t d = stb + (uint32_t)(r * FQ_ST + seg * 16);
            cp_async16(d, khi + go);
            cp_async16(d + SK_SPLIT, klo + go);
        }
#pragma unroll
        for (int t = 0; t < 4; ++t) {
            int idx = t * 256 + tid;
            int dd = idx >> 3, seg = idx & 7;
            size_t go = (((size_t)b * KVH_ + hk) * HD_ + dd) * S_ + j * 64 + seg * 8;
            uint32_t d = stb + 2 * SK_SPLIT + (uint32_t)(dd * FV_ST + seg * 16);
            cp_async16(d, vthi + go);
            cp_async16(d + SV_SPLIT, vtlo + go);
        }
        asm volatile("cp.async.commit_group;" ::: "memory");
    };

    // prologue: Q into buffer 2, KV tiles 0/1 into buffers 0/1
    {
        const uint32_t st2 = sb + 2 * FSTAGE;
#pragma unroll
        for (int t = 0; t < 8; ++t) {
            int idx = t * 256 + tid;
            int r = idx >> 4, seg = idx & 15;
            size_t go = (((size_t)b * S_ + q0 + r) * H_ + h) * HD_ + seg * 8;
            uint32_t d = st2 + (uint32_t)(r * FQ_ST + seg * 16);
            cp_async16(d, qhi + go);
            cp_async16(d + QLO_OFF, qlo + go);
        }
        asm volatile("cp.async.commit_group;" ::: "memory");
    }
    load_tile(0, 0);
    load_tile(1, 1);

    asm volatile("cp.async.wait_group 2;" ::: "memory");
    __syncthreads();
    uint32_t qh[8][4], ql[8][4];
    {
        const uint32_t st2 = sb + 2 * FSTAGE;
#pragma unroll
        for (int k16 = 0; k16 < 8; ++k16) {
            uint32_t offA = (uint32_t)((w * 16 + (lane & 15)) * FQ_ST +
                                       (k16 * 16 + ((lane >> 4) << 3)) * 2);
            ldmatrix_x4(qh[k16], st2 + offA);
            ldmatrix_x4(ql[k16], st2 + QLO_OFF + offA);
        }
    }
    __syncthreads();

    float o[16][4];
#pragma unroll
    for (int nf = 0; nf < 16; ++nf)
#pragma unroll
        for (int e = 0; e < 4; ++e) o[nf][e] = 0.f;
    float mA = -1e30f, mB = -1e30f, lA = 0.f, lB = 0.f;

    const int rowTopA = q0 + w * 16 + 15;

    for (int i = 0; i < ntiles; ++i) {
        if (i + 1 < ntiles) asm volatile("cp.async.wait_group 1;" ::: "memory");
        else                asm volatile("cp.async.wait_group 0;" ::: "memory");
        __syncthreads();
        if (i + 2 < ntiles) load_tile(i + 2, (i + 2) % 3);

        const bool active = rowTopA >= i * 64;
        if (active) {
            const uint32_t st = sb + (i % 3) * FSTAGE;

            float c[8][4];
#pragma unroll
            for (int nf = 0; nf < 8; ++nf)
#pragma unroll
                for (int e = 0; e < 4; ++e) c[nf][e] = 0.f;

#pragma unroll
            for (int k16 = 0; k16 < 8; ++k16) {
                uint32_t bh[4][4], bl[4][4];
#pragma unroll
                for (int nf2 = 0; nf2 < 4; ++nf2) {
                    uint32_t offB = (uint32_t)((nf2 * 16 + (lane & 7) + ((lane >> 4) << 3)) * FQ_ST +
                                               (k16 * 16 + (((lane >> 3) & 1) << 3)) * 2);
                    ldmatrix_x4(bh[nf2], st + offB);
                    ldmatrix_x4(bl[nf2], st + SK_SPLIT + offB);
                }
#pragma unroll
                for (int nf = 0; nf < 8; ++nf) {
                    uint32_t b0h = bh[nf >> 1][(nf & 1) * 2], b1h = bh[nf >> 1][(nf & 1) * 2 + 1];
                    uint32_t b0l = bl[nf >> 1][(nf & 1) * 2], b1l = bl[nf >> 1][(nf & 1) * 2 + 1];
                    mma_f16(c[nf], qh[k16], b0h, b1h);
                    mma_f16(c[nf], qh[k16], b0l, b1l);
                    mma_f16(c[nf], ql[k16], b0h, b1h);
                }
            }

            if (i >= 2 * qt) {
                int rowA = q0 + w * 16 + (lane >> 2);
                int colb = i * 64 + (lane & 3) * 2;
#pragma unroll
                for (int nf = 0; nf < 8; ++nf) {
                    int c0 = colb + nf * 8, c1 = c0 + 1;
                    if (c0 > rowA) c[nf][0] = -1e30f;
                    if (c1 > rowA) c[nf][1] = -1e30f;
                    if (c0 > rowA + 8) c[nf][2] = -1e30f;
                    if (c1 > rowA + 8) c[nf][3] = -1e30f;
                }
            }

            float mtA = -1e30f, mtB = -1e30f;
#pragma unroll
            for (int nf = 0; nf < 8; ++nf) {
                mtA = fmaxf(mtA, fmaxf(c[nf][0], c[nf][1]));
                mtB = fmaxf(mtB, fmaxf(c[nf][2], c[nf][3]));
            }
            mtA = fmaxf(mtA, __shfl_xor_sync(0xffffffffu, mtA, 1));
            mtA = fmaxf(mtA, __shfl_xor_sync(0xffffffffu, mtA, 2));
            mtB = fmaxf(mtB, __shfl_xor_sync(0xffffffffu, mtB, 1));
            mtB = fmaxf(mtB, __shfl_xor_sync(0xffffffffu, mtB, 2));
            float mnA = fmaxf(mA, mtA), mnB = fmaxf(mB, mtB);
            float aA = ex2f(mA - mnA), aB = ex2f(mB - mnB);
            mA = mnA; mB = mnB;
            float rsA = 0.f, rsB = 0.f;
#pragma unroll
            for (int nf = 0; nf < 8; ++nf) {
                c[nf][0] = ex2f(c[nf][0] - mnA);
                c[nf][1] = ex2f(c[nf][1] - mnA);
                c[nf][2] = ex2f(c[nf][2] - mnB);
                c[nf][3] = ex2f(c[nf][3] - mnB);
                rsA += c[nf][0] + c[nf][1];
                rsB += c[nf][2] + c[nf][3];
            }
            rsA += __shfl_xor_sync(0xffffffffu, rsA, 1);
            rsA += __shfl_xor_sync(0xffffffffu, rsA, 2);
            rsB += __shfl_xor_sync(0xffffffffu, rsB, 1);
            rsB += __shfl_xor_sync(0xffffffffu, rsB, 2);
            lA = lA * aA + rsA;
            lB = lB * aB + rsB;
#pragma unroll
            for (int nf = 0; nf < 16; ++nf) {
                o[nf][0] *= aA; o[nf][1] *= aA;
                o[nf][2] *= aB; o[nf][3] *= aB;
            }

            const uint32_t stv = st + 2 * SK_SPLIT;
#pragma unroll
            for (int kc = 0; kc < 4; ++kc) {
                uint32_t ph[4], pl[4];
                split_pack_h(c[2 * kc][0],     c[2 * kc][1],     ph[0], pl[0]);
                split_pack_h(c[2 * kc][2],     c[2 * kc][3],     ph[1], pl[1]);
                split_pack_h(c[2 * kc + 1][0], c[2 * kc + 1][1], ph[2], pl[2]);
                split_pack_h(c[2 * kc + 1][2], c[2 * kc + 1][3], ph[3], pl[3]);
#pragma unroll
                for (int nf2 = 0; nf2 < 8; ++nf2) {
                    uint32_t offV = (uint32_t)((nf2 * 16 + (lane & 7) + ((lane >> 4) << 3)) * FV_ST +
                                               (kc * 16 + (((lane >> 3) & 1) << 3)) * 2);
                    uint32_t vh[4], vl[4];
                    ldmatrix_x4(vh, stv + offV);
                    ldmatrix_x4(vl, stv + SV_SPLIT + offV);
#pragma unroll
                    for (int t = 0; t < 2; ++t) {
                        int nf = nf2 * 2 + t;
                        mma_f16(o[nf], ph, vh[t * 2], vh[t * 2 + 1]);
                        mma_f16(o[nf], ph, vl[t * 2], vl[t * 2 + 1]);
                        mma_f16(o[nf], pl, vh[t * 2], vh[t * 2 + 1]);
                    }
                }
            }
        }
    }

    float iA = 1.f / lA, iB = 1.f / lB;
    int rowA = q0 + w * 16 + (lane >> 2);
#pragma unroll
    for (int nf = 0; nf < 16; ++nf) {
        int dcol = nf * 8 + (lane & 3) * 2;
        size_t oA = (((size_t)b * S_ + rowA) * H_ + h) * HD_ + dcol;
        size_t oB = (((size_t)b * S_ + rowA + 8) * H_ + h) * HD_ + dcol;
        store_split2h(athi, atlo, oA, o[nf][0] * iA, o[nf][1] * iA);
        store_split2h(athi, atlo, oB, o[nf][2] * iB, o[nf][3] * iB);
    }
}

// ---------------- host ----------------
extern "C" void kernel_launch(void* const* d_in, const int* in_sizes, int n_in,
                              void* d_out, int out_size) {
    const float* x       = (const float*)d_in[0];
    const float* wq      = (const float*)d_in[1];
    const float* wk      = (const float*)d_in[2];
    const float* wv      = (const float*)d_in[3];
    const float* wo      = (const float*)d_in[4];
    const float* pos_cos = (const float*)d_in[5];
    const float* pos_sin = (const float*)d_in[6];
    float* out = (float*)d_out;

    float* v;
    cudaGetSymbolAddress((void**)&v, g_v);
    __half *xhi, *xlo, *wqh, *wkh, *wvh, *woh, *athi, *atlo;
    __half *qhi, *qlo, *khi, *klo, *vthi, *vtlo;
    cudaGetSymbolAddress((void**)&xhi, g_xhi);  cudaGetSymbolAddress((void**)&xlo, g_xlo);
    cudaGetSymbolAddress((void**)&wqh, g_wqh);  cudaGetSymbolAddress((void**)&wkh, g_wkh);
    cudaGetSymbolAddress((void**)&wvh, g_wvh);  cudaGetSymbolAddress((void**)&woh, g_woh);
    cudaGetSymbolAddress((void**)&athi, g_athi); cudaGetSymbolAddress((void**)&atlo, g_atlo);
    cudaGetSymbolAddress((void**)&qhi, g_qhi);  cudaGetSymbolAddress((void**)&qlo, g_qlo);
    cudaGetSymbolAddress((void**)&khi, g_khi);  cudaGetSymbolAddress((void**)&klo, g_klo);
    cudaGetSymbolAddress((void**)&vthi, g_vthi); cudaGetSymbolAddress((void**)&vtlo, g_vtlo);

    const int M = MSZ;          // 8192
    const int KV = KVH_ * HD_;  // 1024
    const float qscale = 0.08838834764831845f * 1.4426950408889634f;  // 1/sqrt(HD) * log2(e)

    // conversions
    {
        size_t nx = (size_t)M * D_;
        split_kernel<<<(unsigned)((nx + 255) / 256), 256>>>(x, xhi, xlo, nx);
        whalf_t_kernel<<<dim3(D_ / 32, D_ / 32), dim3(32, 8)>>>(wq, wqh, D_, D_);
        whalf_t_kernel<<<dim3(KV / 32, D_ / 32), dim3(32, 8)>>>(wk, wkh, D_, KV);
        whalf_t_kernel<<<dim3(KV / 32, D_ / 32), dim3(32, 8)>>>(wv, wvh, D_, KV);
        whalf_t_kernel<<<dim3(D_ / 32, D_ / 32), dim3(32, 8)>>>(wo, woh, D_, D_);
    }

    cudaFuncSetAttribute(gemm2, cudaFuncAttributeMaxDynamicSharedMemorySize, GEMM_SMEM);

    // Q/K projections with fused RoPE(+scale)+split epilogue; V projection plain fp32
    gemm2<<<dim3(D_ / 128, M / 128), 256, GEMM_SMEM>>>(xhi, xlo, wqh, nullptr, qhi, qlo,
                                                       pos_cos, pos_sin, qscale, M, D_, D_, 1);
    gemm2<<<dim3(KV / 128, M / 128), 256, GEMM_SMEM>>>(xhi, xlo, wkh, nullptr, khi, klo,
                                                       pos_cos, pos_sin, 1.0f, M, KV, D_, 1);
    gemm2<<<dim3(KV / 128, M / 128), 256, GEMM_SMEM>>>(xhi, xlo, wvh, v, nullptr, nullptr,
                                                       nullptr, nullptr, 0.f, M, KV, D_, 0);

    // V transpose + split
    vsplit_t_kernel<<<dim3(HD_ / 32, S_ / 32, B_ * KVH_), dim3(32, 8)>>>(v, vthi, vtlo);

    // flash attention (fp16 3-pass) -> athi/atlo
    cudaFuncSetAttribute(flash_mma, cudaFuncAttributeMaxDynamicSharedMemorySize, FLASH_SMEM);
    flash_mma<<<dim3(S_ / 128, H_, B_), 256, FLASH_SMEM>>>(qhi, qlo, khi, klo, vthi, vtlo, athi, atlo);

    // output projection -> d_out
    gemm2<<<dim3(D_ / 128, M / 128), 256, GEMM_SMEM>>>(athi, atlo, woh, out, nullptr, nullptr,
                                                       nullptr, nullptr, 0.f, M, D_, D_, 0);
}